// round 14
// baseline (speedup 1.0000x reference)
#include <cuda_runtime.h>
#include <cuda_fp16.h>
#include <math.h>

#define DIM     256
#define SEQ     1024
#define BATCH   16
#define NHEADS  8
#define HDIM    32
#define MROWS   (BATCH * SEQ)          /* 16384 */
#define BUFSZ   ((size_t)MROWS * DIM)  /* 4194304 elements */

// ---------------------------------------------------------------------------
// scratch pool (bytes)
// ---------------------------------------------------------------------------
#define P_OUTIMG  (0ull)                         /* 16384x768 h : 24 MB */
#define P_OUTTXT  (P_OUTIMG + 25165824ull)
#define P_AOI     (P_OUTTXT + 25165824ull)       /* 16384x256 h : 8 MB */
#define P_AOT     (P_AOI    + 8388608ull)
#define P_QIMG    (P_AOT    + 8388608ull)
#define P_QTXT    (P_QIMG   + 8388608ull)
#define P_WIMG    (P_QTXT   + 8388608ull)        /* 256x768 h */
#define P_WTXT    (P_WIMG   + 393216ull)
#define P_WOI     (P_WTXT   + 393216ull)         /* 256x256 h */
#define P_WOT     (P_WOI    + 131072ull)
#define P_WENH    (P_WOT    + 131072ull)         /* 512x256 h */
#define P_BIMG    (P_WENH   + 262144ull)         /* 768 f32 */
#define P_BTXT    (P_BIMG   + 4096ull)
#define P_END     (P_BTXT   + 4096ull)

__device__ __align__(256) unsigned char g_pool[P_END];

// ---------------------------------------------------------------------------
// helpers
// ---------------------------------------------------------------------------
__device__ __forceinline__ unsigned f2h2(float lo, float hi) {
    unsigned u;
    asm("cvt.rn.f16x2.f32 %0, %1, %2;" : "=r"(u) : "f"(hi), "f"(lo));
    return u;
}
__device__ __forceinline__ unsigned h2ex2(unsigned x) {
    unsigned r;
    asm("ex2.approx.f16x2 %0, %1;" : "=r"(r) : "r"(x));
    return r;
}
__device__ __forceinline__ void mma_f16(
    float& c0, float& c1, float& c2, float& c3,
    unsigned a0, unsigned a1, unsigned a2, unsigned a3,
    unsigned b0, unsigned b1)
{
    asm volatile(
        "mma.sync.aligned.m16n8k16.row.col.f32.f16.f16.f32 "
        "{%0,%1,%2,%3}, {%4,%5,%6,%7}, {%8,%9}, {%0,%1,%2,%3};"
        : "+f"(c0), "+f"(c1), "+f"(c2), "+f"(c3)
        : "r"(a0), "r"(a1), "r"(a2), "r"(a3), "r"(b0), "r"(b1));
}
__device__ __forceinline__ void ldsm_x4(
    unsigned& r0, unsigned& r1, unsigned& r2, unsigned& r3, unsigned addr)
{
    asm volatile("ldmatrix.sync.aligned.m8n8.x4.shared.b16 {%0,%1,%2,%3}, [%4];"
        : "=r"(r0), "=r"(r1), "=r"(r2), "=r"(r3) : "r"(addr));
}
__device__ __forceinline__ void ldsm_x4_t(
    unsigned& r0, unsigned& r1, unsigned& r2, unsigned& r3, unsigned addr)
{
    asm volatile("ldmatrix.sync.aligned.m8n8.x4.trans.shared.b16 {%0,%1,%2,%3}, [%4];"
        : "=r"(r0), "=r"(r1), "=r"(r2), "=r"(r3) : "r"(addr));
}
__device__ __forceinline__ unsigned smem_u32(const void* p) {
    return (unsigned)__cvta_generic_to_shared(p);
}
__device__ __forceinline__ void cp16(unsigned dst, const void* src) {
    asm volatile("cp.async.cg.shared.global [%0], [%1], 16;" :: "r"(dst), "l"(src));
}
__device__ __forceinline__ void cp_commit() { asm volatile("cp.async.commit_group;"); }
__device__ __forceinline__ void cp_wait0()  { asm volatile("cp.async.wait_group 0;"); }
__device__ __forceinline__ void cp_wait1()  { asm volatile("cp.async.wait_group 1;"); }

// ---------------------------------------------------------------------------
// prep: weights only (R8 layout). Work items (float4):
//  [0, 98304)        Wimg/Wtxt QKV pack (2x49152)
//  [98304, 163840)   WoI/WoT/Wenh convert (16384+16384+32768)
//  [163840, 164224)  bias concat (2x192)
// ---------------------------------------------------------------------------
__global__ void prep_weights_kernel(
    const float* __restrict__ i2t_wq, const float* __restrict__ i2t_wk,
    const float* __restrict__ i2t_wv, const float* __restrict__ t2i_wq,
    const float* __restrict__ t2i_wk, const float* __restrict__ t2i_wv,
    const float* __restrict__ i2t_bq, const float* __restrict__ i2t_bk,
    const float* __restrict__ i2t_bv, const float* __restrict__ t2i_bq,
    const float* __restrict__ t2i_bk, const float* __restrict__ t2i_bv,
    const float* __restrict__ i2t_wo, const float* __restrict__ t2i_wo,
    const float* __restrict__ enh_w,
    __half* __restrict__ Wimg, __half* __restrict__ Wtxt,
    __half* __restrict__ WoI,  __half* __restrict__ WoT,
    __half* __restrict__ Wenh,
    float* __restrict__ bimg, float* __restrict__ btxt)
{
    int i = blockIdx.x * blockDim.x + threadIdx.x;
    if (i < 98304) {
        int pick = (i >= 49152);
        int g = pick ? i - 49152 : i;
        const float* w0 = pick ? t2i_wq : i2t_wq;
        const float* w1 = pick ? i2t_wk : t2i_wk;
        const float* w2 = pick ? i2t_wv : t2i_wv;
        __half* Wd = pick ? Wtxt : Wimg;
        int k = g / 192, jj = (g % 192) * 4;
        const float* src = (jj < 256) ? w0 : (jj < 512) ? w1 : w2;
        float4 v = *(const float4*)(src + k * 256 + (jj & 255));
        uint2 u;
        u.x = f2h2(v.x, v.y);
        u.y = f2h2(v.z, v.w);
        *(uint2*)(Wd + k * 768 + jj) = u;
    } else if (i < 163840) {
        int j = i - 98304;
        const float* s; __half* d;
        if (j < 16384)      { s = i2t_wo; d = WoI; }
        else if (j < 32768) { s = t2i_wo; d = WoT; j -= 16384; }
        else                { s = enh_w;  d = Wenh; j -= 32768; }
        float4 v = ((const float4*)s)[j];
        uint2 u;
        u.x = f2h2(v.x, v.y);
        u.y = f2h2(v.z, v.w);
        ((uint2*)d)[j] = u;
    } else if (i < 164224) {
        int pick = (i >= 164032);
        int g = pick ? i - 164032 : i - 163840;    // 0..191
        const float* b0 = pick ? t2i_bq : i2t_bq;
        const float* b1 = pick ? i2t_bk : t2i_bk;
        const float* b2 = pick ? i2t_bv : t2i_bv;
        float* bd = pick ? btxt : bimg;
        int j4 = g * 4;
        const float* src = (j4 < 256) ? b0 : (j4 < 512) ? b1 : b2;
        *(float4*)(bd + j4) = *(const float4*)(src + (j4 & 255));
    }
}

// ---------------------------------------------------------------------------
// QKV GEMM with FP32 A operand (converted in-kernel), dual-problem.
// 128x128x32 tile, 8 warps (4x2), warp tile 32x64.
// A: LDG fp32 -> cvt -> STS, software-pipelined; B: cp.async fp16 dbl-buffer.
// ---------------------------------------------------------------------------
#define AST 40
#define BST 136
#define ABUF (128 * AST)
#define BBUF (32 * BST)

__global__ void __launch_bounds__(256, 2) gemm_f32a_dual(
    const float* A_0, const __half* W_0, const float* b_0, __half* C_0,
    const float* A_1, const __half* W_1, const float* b_1, __half* C_1,
    int ldc, int N, int K)
{
    __shared__ __align__(16) __half As[2 * ABUF];
    __shared__ __align__(16) __half Bs[2 * BBUF];

    int zz = blockIdx.z;
    const float* A  = zz ? A_1 : A_0;
    const __half* W = zz ? W_1 : W_0;
    const float* bias = zz ? b_1 : b_0;
    __half* C = zz ? C_1 : C_0;

    int tid = threadIdx.x, lane = tid & 31, warp = tid >> 5;
    int wm = warp & 3, wn = warp >> 2;
    int gid = lane >> 2, tig = lane & 3;
    int m0 = blockIdx.y * 128, n0 = blockIdx.x * 128;

    int ar0 = tid >> 2, ac = (tid & 3) * 8;     // A: rows ar0, ar0+64; 8 floats
    int br = tid >> 4,  bc = (tid & 15) * 8;

    unsigned As_b = smem_u32(As), Bs_b = smem_u32(Bs);

    int t3 = lane >> 3, lr = lane & 7, tq = t3 & 1, th = t3 >> 1;
    unsigned a_ln = (unsigned)(((wm * 32 + tq * 8 + lr) * AST + th * 8) * 2);
    unsigned b_ln = (unsigned)(((tq * 8 + lr) * BST + wn * 64 + th * 8) * 2);

    float acc[2][8][4] = {};

    const float* Ar0 = A + (size_t)(m0 + ar0) * DIM + ac;
    const float* Ar1 = A + (size_t)(m0 + ar0 + 64) * DIM + ac;

    auto stageA = [&](int buf, int k0) {
        float4 v0 = *(const float4*)(Ar0 + k0);
        float4 v1 = *(const float4*)(Ar0 + k0 + 4);
        float4 v2 = *(const float4*)(Ar1 + k0);
        float4 v3 = *(const float4*)(Ar1 + k0 + 4);
        uint4 u;
        u.x = f2h2(v0.x, v0.y); u.y = f2h2(v0.z, v0.w);
        u.z = f2h2(v1.x, v1.y); u.w = f2h2(v1.z, v1.w);
        *(uint4*)&As[buf * ABUF + ar0 * AST + ac] = u;
        u.x = f2h2(v2.x, v2.y); u.y = f2h2(v2.z, v2.w);
        u.z = f2h2(v3.x, v3.y); u.w = f2h2(v3.z, v3.w);
        *(uint4*)&As[buf * ABUF + (ar0 + 64) * AST + ac] = u;
    };
    auto issueB = [&](int buf, int k0) {
        unsigned bd = Bs_b + (unsigned)(buf * BBUF * 2);
        cp16(bd + (unsigned)((br * BST + bc) * 2),
             W + (size_t)(k0 + br) * N + n0 + bc);
        cp16(bd + (unsigned)(((br + 16) * BST + bc) * 2),
             W + (size_t)(k0 + br + 16) * N + n0 + bc);
    };

    int T = K / 32;
    stageA(0, 0);
    issueB(0, 0);
    cp_commit();

    for (int it = 0; it < T; it++) {
        bool pf = (it + 1 < T);
        if (pf) {
            issueB((it + 1) & 1, (it + 1) * 32);
            cp_commit();
            cp_wait1();
        } else {
            cp_wait0();
        }
        __syncthreads();

        // prefetch fp32 A for next tile (LDGs in flight during compute)
        float4 v0, v1, v2, v3;
        if (pf) {
            int k0n = (it + 1) * 32;
            v0 = *(const float4*)(Ar0 + k0n);
            v1 = *(const float4*)(Ar0 + k0n + 4);
            v2 = *(const float4*)(Ar1 + k0n);
            v3 = *(const float4*)(Ar1 + k0n + 4);
        }

        unsigned ab = As_b + (unsigned)((it & 1) * ABUF * 2) + a_ln;
        unsigned bb = Bs_b + (unsigned)((it & 1) * BBUF * 2) + b_ln;
        #pragma unroll
        for (int kk = 0; kk < 2; kk++) {
            unsigned af[2][4];
            ldsm_x4(af[0][0], af[0][1], af[0][2], af[0][3], ab + kk * 32);
            ldsm_x4(af[1][0], af[1][1], af[1][2], af[1][3],
                    ab + 16 * AST * 2 + kk * 32);
            unsigned bf[8][2];
            #pragma unroll
            for (int bq = 0; bq < 4; bq++) {
                unsigned r0, r1, r2, r3;
                ldsm_x4_t(r0, r1, r2, r3,
                          bb + (unsigned)(kk * (16 * BST * 2) + bq * 32));
                bf[bq*2][0]   = r0; bf[bq*2][1]   = r1;
                bf[bq*2+1][0] = r2; bf[bq*2+1][1] = r3;
            }
            #pragma unroll
            for (int mt = 0; mt < 2; mt++)
                #pragma unroll
                for (int nt = 0; nt < 8; nt++)
                    mma_f16(acc[mt][nt][0], acc[mt][nt][1],
                            acc[mt][nt][2], acc[mt][nt][3],
                            af[mt][0], af[mt][1], af[mt][2], af[mt][3],
                            bf[nt][0], bf[nt][1]);
        }

        if (pf) {
            int buf = (it + 1) & 1;
            uint4 u;
            u.x = f2h2(v0.x, v0.y); u.y = f2h2(v0.z, v0.w);
            u.z = f2h2(v1.x, v1.y); u.w = f2h2(v1.z, v1.w);
            *(uint4*)&As[buf * ABUF + ar0 * AST + ac] = u;
            u.x = f2h2(v2.x, v2.y); u.y = f2h2(v2.z, v2.w);
            u.z = f2h2(v3.x, v3.y); u.w = f2h2(v3.z, v3.w);
            *(uint4*)&As[buf * ABUF + (ar0 + 64) * AST + ac] = u;
        }
        __syncthreads();
    }

    #pragma unroll
    for (int mt = 0; mt < 2; mt++) {
        #pragma unroll
        for (int nt = 0; nt < 8; nt++) {
            int r = m0 + wm * 32 + mt * 16 + gid;
            int c = n0 + wn * 64 + nt * 8 + tig * 2;
            float b0 = bias[c], b1 = bias[c + 1];
            *(unsigned*)&C[(size_t)r * ldc + c] =
                f2h2(acc[mt][nt][0] + b0, acc[mt][nt][1] + b1);
            *(unsigned*)&C[(size_t)(r + 8) * ldc + c] =
                f2h2(acc[mt][nt][2] + b0, acc[mt][nt][3] + b1);
        }
    }
}

// ---------------------------------------------------------------------------
// FP16 GEMM, dual-problem (R10, frozen): used for enhancement.
// ---------------------------------------------------------------------------
template<int OUT_HALF>
__global__ void __launch_bounds__(256, 2) gemm_f16_dual(
    const __half* A1_0, const __half* A2_0, const __half* W_0,
    const float* b_0, void* C_0,
    const __half* A1_1, const __half* A2_1, const __half* W_1,
    const float* b_1, void* C_1,
    int ksplit, int ldc, int N, int K)
{
    __shared__ __align__(16) __half As[2 * ABUF];
    __shared__ __align__(16) __half Bs[2 * BBUF];

    int zz = blockIdx.z;
    const __half* A1 = zz ? A1_1 : A1_0;
    const __half* A2 = zz ? A2_1 : A2_0;
    const __half* W  = zz ? W_1  : W_0;
    const float* bias = zz ? b_1 : b_0;
    void* Cv = zz ? C_1 : C_0;

    int tid = threadIdx.x, lane = tid & 31, warp = tid >> 5;
    int wm = warp & 3, wn = warp >> 2;
    int gid = lane >> 2, tig = lane & 3;
    int m0 = blockIdx.y * 128, n0 = blockIdx.x * 128;

    int ar0 = tid >> 2, ac = (tid & 3) * 8;
    int br = tid >> 4,  bc = (tid & 15) * 8;

    unsigned As_b = smem_u32(As), Bs_b = smem_u32(Bs);

    int t3 = lane >> 3, lr = lane & 7, tq = t3 & 1, th = t3 >> 1;
    unsigned a_ln = (unsigned)(((wm * 32 + tq * 8 + lr) * AST + th * 8) * 2);
    unsigned b_ln = (unsigned)(((tq * 8 + lr) * BST + wn * 64 + th * 8) * 2);

    float acc[2][8][4] = {};

    auto issue = [&](int buf, int k0) {
        const __half* Ah = (k0 < ksplit) ? (A1 + k0) : (A2 + (k0 - ksplit));
        unsigned ad = As_b + (unsigned)(buf * ABUF * 2);
        cp16(ad + (unsigned)((ar0 * AST + ac) * 2),
             Ah + (size_t)(m0 + ar0) * DIM + ac);
        cp16(ad + (unsigned)(((ar0 + 64) * AST + ac) * 2),
             Ah + (size_t)(m0 + ar0 + 64) * DIM + ac);
        unsigned bd = Bs_b + (unsigned)(buf * BBUF * 2);
        cp16(bd + (unsigned)((br * BST + bc) * 2),
             W + (size_t)(k0 + br) * N + n0 + bc);
        cp16(bd + (unsigned)(((br + 16) * BST + bc) * 2),
             W + (size_t)(k0 + br + 16) * N + n0 + bc);
    };

    int T = K / 32;
    issue(0, 0);
    cp_commit();

    for (int it = 0; it < T; it++) {
        if (it + 1 < T) {
            issue((it + 1) & 1, (it + 1) * 32);
            cp_commit();
            cp_wait1();
        } else {
            cp_wait0();
        }
        __syncthreads();

        unsigned ab = As_b + (unsigned)((it & 1) * ABUF * 2) + a_ln;
        unsigned bb = Bs_b + (unsigned)((it & 1) * BBUF * 2) + b_ln;
        #pragma unroll
        for (int kk = 0; kk < 2; kk++) {
            unsigned af[2][4];
            ldsm_x4(af[0][0], af[0][1], af[0][2], af[0][3], ab + kk * 32);
            ldsm_x4(af[1][0], af[1][1], af[1][2], af[1][3],
                    ab + 16 * AST * 2 + kk * 32);
            unsigned bf[8][2];
            #pragma unroll
            for (int bq = 0; bq < 4; bq++) {
                unsigned r0, r1, r2, r3;
                ldsm_x4_t(r0, r1, r2, r3,
                          bb + (unsigned)(kk * (16 * BST * 2) + bq * 32));
                bf[bq*2][0]   = r0; bf[bq*2][1]   = r1;
                bf[bq*2+1][0] = r2; bf[bq*2+1][1] = r3;
            }
            #pragma unroll
            for (int mt = 0; mt < 2; mt++)
                #pragma unroll
                for (int nt = 0; nt < 8; nt++)
                    mma_f16(acc[mt][nt][0], acc[mt][nt][1],
                            acc[mt][nt][2], acc[mt][nt][3],
                            af[mt][0], af[mt][1], af[mt][2], af[mt][3],
                            bf[nt][0], bf[nt][1]);
        }
        __syncthreads();
    }

    #pragma unroll
    for (int mt = 0; mt < 2; mt++) {
        #pragma unroll
        for (int nt = 0; nt < 8; nt++) {
            int r = m0 + wm * 32 + mt * 16 + gid;
            int c = n0 + wn * 64 + nt * 8 + tig * 2;
            float b0 = bias[c], b1 = bias[c + 1];
            float x0 = acc[mt][nt][0] + b0, x1 = acc[mt][nt][1] + b1;
            float x2 = acc[mt][nt][2] + b0, x3 = acc[mt][nt][3] + b1;
            if (OUT_HALF) {
                __half* C = (__half*)Cv;
                *(unsigned*)&C[(size_t)r * ldc + c]       = f2h2(x0, x1);
                *(unsigned*)&C[(size_t)(r + 8) * ldc + c] = f2h2(x2, x3);
            } else {
                float* C = (float*)Cv;
                C[(size_t)r * ldc + c]           = x0;
                C[(size_t)r * ldc + c + 1]       = x1;
                C[(size_t)(r + 8) * ldc + c]     = x2;
                C[(size_t)(r + 8) * ldc + c + 1] = x3;
            }
        }
    }
}

// ---------------------------------------------------------------------------
// Fused O-projection + bias + residual(FP32) + LayerNorm + f2h (R12, frozen).
// ---------------------------------------------------------------------------
#define OAST 40
#define OBST 264
#define OABUF (64 * OAST)
#define OBBUF (32 * OBST)

__global__ void __launch_bounds__(256, 2) oproj_ln_dual(
    const __half* __restrict__ AO_0, const __half* __restrict__ Wo_0,
    const float* __restrict__ bo_0, const float* __restrict__ R_0,
    const float* __restrict__ g_0, const float* __restrict__ be_0,
    __half* __restrict__ O_0,
    const __half* __restrict__ AO_1, const __half* __restrict__ Wo_1,
    const float* __restrict__ bo_1, const float* __restrict__ R_1,
    const float* __restrict__ g_1, const float* __restrict__ be_1,
    __half* __restrict__ O_1)
{
    __shared__ __align__(16) __half As[2 * OABUF];
    __shared__ __align__(16) __half Bs[2 * OBBUF];
    __shared__ float psum[64][4];
    __shared__ float psq[64][4];
    __shared__ float murs[64][2];

    int zz = blockIdx.y;
    const __half* AO = zz ? AO_1 : AO_0;
    const __half* Wo = zz ? Wo_1 : Wo_0;
    const float* bo  = zz ? bo_1 : bo_0;
    const float* R   = zz ? R_1  : R_0;
    const float* gam = zz ? g_1  : g_0;
    const float* bet = zz ? be_1 : be_0;
    __half* O = zz ? O_1 : O_0;

    int tid = threadIdx.x, lane = tid & 31, warp = tid >> 5;
    int wm = warp & 1, wn = warp >> 1;
    int gid = lane >> 2, tig = lane & 3;
    int m0 = blockIdx.x * 64;

    int ar0 = tid >> 2, ac = (tid & 3) * 8;
    int br  = tid >> 5, bc = (tid & 31) * 8;

    unsigned As_b = smem_u32(As), Bs_b = smem_u32(Bs);

    int t3 = lane >> 3, lr = lane & 7, tq = t3 & 1, th = t3 >> 1;
    unsigned a_ln = (unsigned)(((wm * 32 + tq * 8 + lr) * OAST + th * 8) * 2);
    unsigned b_ln = (unsigned)(((tq * 8 + lr) * OBST + wn * 64 + th * 8) * 2);

    float acc[2][8][4] = {};

    auto issue = [&](int buf, int k0) {
        unsigned ad = As_b + (unsigned)(buf * OABUF * 2);
        cp16(ad + (unsigned)((ar0 * OAST + ac) * 2),
             AO + (size_t)(m0 + ar0) * DIM + k0 + ac);
        unsigned bd = Bs_b + (unsigned)(buf * OBBUF * 2);
        #pragma unroll
        for (int i = 0; i < 4; i++)
            cp16(bd + (unsigned)(((br + i * 8) * OBST + bc) * 2),
                 Wo + (size_t)(k0 + br + i * 8) * DIM + bc);
    };

    const int T = DIM / 32;
    issue(0, 0);
    cp_commit();

    for (int it = 0; it < T; it++) {
        if (it + 1 < T) {
            issue((it + 1) & 1, (it + 1) * 32);
            cp_commit();
            cp_wait1();
        } else {
            cp_wait0();
        }
        __syncthreads();

        unsigned ab = As_b + (unsigned)((it & 1) * OABUF * 2) + a_ln;
        unsigned bb = Bs_b + (unsigned)((it & 1) * OBBUF * 2) + b_ln;
        #pragma unroll
        for (int kk = 0; kk < 2; kk++) {
            unsigned af[2][4];
            ldsm_x4(af[0][0], af[0][1], af[0][2], af[0][3], ab + kk * 32);
            ldsm_x4(af[1][0], af[1][1], af[1][2], af[1][3],
                    ab + 16 * OAST * 2 + kk * 32);
            unsigned bf[8][2];
            #pragma unroll
            for (int bq = 0; bq < 4; bq++) {
                unsigned r0, r1, r2, r3;
                ldsm_x4_t(r0, r1, r2, r3,
                          bb + (unsigned)(kk * (16 * OBST * 2) + bq * 32));
                bf[bq*2][0]   = r0; bf[bq*2][1]   = r1;
                bf[bq*2+1][0] = r2; bf[bq*2+1][1] = r3;
            }
            #pragma unroll
            for (int mt = 0; mt < 2; mt++)
                #pragma unroll
                for (int nt = 0; nt < 8; nt++)
                    mma_f16(acc[mt][nt][0], acc[mt][nt][1],
                            acc[mt][nt][2], acc[mt][nt][3],
                            af[mt][0], af[mt][1], af[mt][2], af[mt][3],
                            bf[nt][0], bf[nt][1]);
        }
        __syncthreads();
    }

    #pragma unroll
    for (int mt = 0; mt < 2; mt++) {
        int r1 = m0 + wm * 32 + mt * 16 + gid;
        float s1 = 0.f, q1 = 0.f, s2 = 0.f, q2 = 0.f;
        #pragma unroll
        for (int nt = 0; nt < 8; nt++) {
            int c = wn * 64 + nt * 8 + tig * 2;
            float b0 = bo[c], b1 = bo[c + 1];
            float2 rv1 = *(const float2*)&R[(size_t)r1 * DIM + c];
            float2 rv2 = *(const float2*)&R[(size_t)(r1 + 8) * DIM + c];
            float x0 = acc[mt][nt][0] + b0 + rv1.x;
            float x1 = acc[mt][nt][1] + b1 + rv1.y;
            float x2 = acc[mt][nt][2] + b0 + rv2.x;
            float x3 = acc[mt][nt][3] + b1 + rv2.y;
            acc[mt][nt][0] = x0; acc[mt][nt][1] = x1;
            acc[mt][nt][2] = x2; acc[mt][nt][3] = x3;
            s1 += x0 + x1;
            q1 = fmaf(x0, x0, q1); q1 = fmaf(x1, x1, q1);
            s2 += x2 + x3;
            q2 = fmaf(x2, x2, q2); q2 = fmaf(x3, x3, q2);
        }
        #pragma unroll
        for (int off = 1; off <= 2; off <<= 1) {
            s1 += __shfl_xor_sync(0xFFFFFFFFu, s1, off);
            q1 += __shfl_xor_sync(0xFFFFFFFFu, q1, off);
            s2 += __shfl_xor_sync(0xFFFFFFFFu, s2, off);
            q2 += __shfl_xor_sync(0xFFFFFFFFu, q2, off);
        }
        if (tig == 0) {
            int rl = wm * 32 + mt * 16 + gid;
            psum[rl][wn] = s1;  psq[rl][wn] = q1;
            psum[rl + 8][wn] = s2;  psq[rl + 8][wn] = q2;
        }
    }
    __syncthreads();

    if (tid < 64) {
        float ss = psum[tid][0] + psum[tid][1] + psum[tid][2] + psum[tid][3];
        float qq = psq[tid][0] + psq[tid][1] + psq[tid][2] + psq[tid][3];
        float mu = ss * (1.f / 256.f);
        float var = qq * (1.f / 256.f) - mu * mu;
        murs[tid][0] = mu;
        murs[tid][1] = rsqrtf(var + 1e-5f);
    }
    __syncthreads();

    #pragma unroll
    for (int mt = 0; mt < 2; mt++) {
        int rl = wm * 32 + mt * 16 + gid;
        float mu1 = murs[rl][0],     rs1 = murs[rl][1];
        float mu2 = murs[rl + 8][0], rs2 = murs[rl + 8][1];
        int r1 = m0 + rl;
        #pragma unroll
        for (int nt = 0; nt < 8; nt++) {
            int c = wn * 64 + nt * 8 + tig * 2;
            float g0 = gam[c], g1 = gam[c + 1];
            float e0 = bet[c], e1 = bet[c + 1];
            *(unsigned*)&O[(size_t)r1 * DIM + c] =
                f2h2((acc[mt][nt][0] - mu1) * rs1 * g0 + e0,
                     (acc[mt][nt][1] - mu1) * rs1 * g1 + e1);
            *(unsigned*)&O[(size_t)(r1 + 8) * DIM + c] =
                f2h2((acc[mt][nt][2] - mu2) * rs2 * g0 + e0,
                     (acc[mt][nt][3] - mu2) * rs2 * g1 + e1);
        }
    }
}

// ---------------------------------------------------------------------------
// FP16 flash attention (R9, frozen).
// ---------------------------------------------------------------------------
#define KST 40
#define KVBUF (64 * KST)

__global__ void __launch_bounds__(256) attn_f16(
    const __half* __restrict__ OutImg, const __half* __restrict__ OutTxt,
    __half* __restrict__ AOi, __half* __restrict__ AOt)
{
    __shared__ __align__(16) __half Ks[2 * KVBUF];
    __shared__ __align__(16) __half Vs[2 * KVBUF];

    int tid = threadIdx.x, lane = tid & 31, warp = tid >> 5;
    int gid = lane >> 2, tig = lane & 3;
    int zz = blockIdx.z;
    int dir = zz >> 4, b = zz & 15;
    const __half* Q  = dir ? OutTxt : OutImg;
    const __half* Kp = (dir ? OutImg : OutTxt) + 256;
    const __half* Vp = (dir ? OutImg : OutTxt) + 512;
    __half* O = dir ? AOt : AOi;
    const int ldin = 768;

    int h = blockIdx.y;
    int q0 = blockIdx.x * 256 + warp * 32;
    int hoff = h * HDIM;
    size_t rowQ = (size_t)b * SEQ + q0;

    int s_row = tid >> 2, s_c = (tid & 3) * 8;

    unsigned Ks_b = smem_u32(Ks), Vs_b = smem_u32(Vs);

    int t3 = lane >> 3, lr = lane & 7, tq = t3 & 1, th = t3 >> 1;
    unsigned kv_ln = (unsigned)(((tq * 8 + lr) * KST + th * 8) * 2);

    const __half2 c2h = __float2half2_rn(0.25503526f);
    unsigned qf[2][2][4];
    #pragma unroll
    for (int rs = 0; rs < 2; rs++) {
        #pragma unroll
        for (int kk = 0; kk < 2; kk++) {
            const __half* q1 = Q + (rowQ + rs * 16 + gid) * ldin + hoff + kk * 16 + tig * 2;
            const __half* q2 = q1 + 8 * ldin;
            __half2 v;
            v = __hmul2(*(const __half2*)q1,       c2h); qf[rs][kk][0] = *(unsigned*)&v;
            v = __hmul2(*(const __half2*)q2,       c2h); qf[rs][kk][1] = *(unsigned*)&v;
            v = __hmul2(*(const __half2*)(q1 + 8), c2h); qf[rs][kk][2] = *(unsigned*)&v;
            v = __hmul2(*(const __half2*)(q2 + 8), c2h); qf[rs][kk][3] = *(unsigned*)&v;
        }
    }

    const unsigned ONES = 0x3C003C00u;
    float o[2][4][4] = {};
    float ol[2][4] = {};

    auto issue = [&](int buf, int kt) {
        size_t g = ((size_t)b * SEQ + kt + s_row) * ldin + hoff + s_c;
        unsigned off = (unsigned)(buf * KVBUF * 2) + (unsigned)((s_row * KST + s_c) * 2);
        cp16(Ks_b + off, Kp + g);
        cp16(Vs_b + off, Vp + g);
    };

    issue(0, 0);
    cp_commit();

    const int T = SEQ / 64;
    for (int it = 0; it < T; it++) {
        if (it + 1 < T) {
            issue((it + 1) & 1, (it + 1) * 64);
            cp_commit();
            cp_wait1();
        } else {
            cp_wait0();
        }
        __syncthreads();

        unsigned kb = Ks_b + (unsigned)((it & 1) * KVBUF * 2) + kv_ln;
        unsigned vb = Vs_b + (unsigned)((it & 1) * KVBUF * 2) + kv_ln;

        float s0[8][4] = {}, s1[8][4] = {};
        #pragma unroll
        for (int kk = 0; kk < 2; kk++) {
            #pragma unroll
            for (int np = 0; np < 4; np++) {
                unsigned r0, r1, r2, r3;
                ldsm_x4(r0, r1, r2, r3,
                        kb + (unsigned)((np * 16 * KST + kk * 16) * 2));
                mma_f16(s0[np*2][0], s0[np*2][1], s0[np*2][2], s0[np*2][3],
                        qf[0][kk][0], qf[0][kk][1], qf[0][kk][2], qf[0][kk][3], r0, r2);
                mma_f16(s0[np*2+1][0], s0[np*2+1][1], s0[np*2+1][2], s0[np*2+1][3],
                        qf[0][kk][0], qf[0][kk][1], qf[0][kk][2], qf[0][kk][3], r1, r3);
                mma_f16(s1[np*2][0], s1[np*2][1], s1[np*2][2], s1[np*2][3],
                        qf[1][kk][0], qf[1][kk][1], qf[1][kk][2], qf[1][kk][3], r0, r2);
                mma_f16(s1[np*2+1][0], s1[np*2+1][1], s1[np*2+1][2], s1[np*2+1][3],
                        qf[1][kk][0], qf[1][kk][1], qf[1][kk][2], qf[1][kk][3], r1, r3);
            }
        }

        unsigned pa0[4][4], pa1[4][4];
        #pragma unroll
        for (int kk = 0; kk < 4; kk++) {
            pa0[kk][0] = h2ex2(f2h2(s0[2*kk][0],   s0[2*kk][1]));
            pa0[kk][1] = h2ex2(f2h2(s0[2*kk][2],   s0[2*kk][3]));
            pa0[kk][2] = h2ex2(f2h2(s0[2*kk+1][0], s0[2*kk+1][1]));
            pa0[kk][3] = h2ex2(f2h2(s0[2*kk+1][2], s0[2*kk+1][3]));
            pa1[kk][0] = h2ex2(f2h2(s1[2*kk][0],   s1[2*kk][1]));
            pa1[kk][1] = h2ex2(f2h2(s1[2*kk][2],   s1[2*kk][3]));
            pa1[kk][2] = h2ex2(f2h2(s1[2*kk+1][0], s1[2*kk+1][1]));
            pa1[kk][3] = h2ex2(f2h2(s1[2*kk+1][2], s1[2*kk+1][3]));
        }

        #pragma unroll
        for (int kk = 0; kk < 4; kk++) {
            #pragma unroll
            for (int dg = 0; dg < 2; dg++) {
                unsigned r0, r1, r2, r3;
                ldsm_x4_t(r0, r1, r2, r3,
                          vb + (unsigned)((kk * 16 * KST + dg * 16) * 2));
                mma_f16(o[0][dg*2][0], o[0][dg*2][1], o[0][dg*2][2], o[0][dg*2][3],
                        pa0[kk][0], pa0[kk][1], pa0[kk][2], pa0[kk][3], r0, r1);
                mma_f16(o[0][dg*2+1][0], o[0][dg*2+1][1], o[0][dg*2+1][2], o[0][dg*2+1][3],
                        pa0[kk][0], pa0[kk][1], pa0[kk][2], pa0[kk][3], r2, r3);
                mma_f16(o[1][dg*2][0], o[1][dg*2][1], o[1][dg*2][2], o[1][dg*2][3],
                        pa1[kk][0], pa1[kk][1], pa1[kk][2], pa1[kk][3], r0, r1);
                mma_f16(o[1][dg*2+1][0], o[1][dg*2+1][1], o[1][dg*2+1][2], o[1][dg*2+1][3],
                        pa1[kk][0], pa1[kk][1], pa1[kk][2], pa1[kk][3], r2, r3);
            }
            mma_f16(ol[0][0], ol[0][1], ol[0][2], ol[0][3],
                    pa0[kk][0], pa0[kk][1], pa0[kk][2], pa0[kk][3], ONES, ONES);
            mma_f16(ol[1][0], ol[1][1], ol[1][2], ol[1][3],
                    pa1[kk][0], pa1[kk][1], pa1[kk][2], pa1[kk][3], ONES, ONES);
        }
        __syncthreads();
    }

    #pragma unroll
    for (int rs = 0; rs < 2; rs++) {
        float inv1 = 1.f / ol[rs][0];
        float inv2 = 1.f / ol[rs][2];
        size_t r1 = rowQ + rs * 16 + gid;
        #pragma unroll
        for (int nt = 0; nt < 4; nt++) {
            int col = hoff + nt * 8 + tig * 2;
            *(unsigned*)&O[r1 * DIM + col] =
                f2h2(o[rs][nt][0] * inv1, o[rs][nt][1] * inv1);
            *(unsigned*)&O[(r1 + 8) * DIM + col] =
                f2h2(o[rs][nt][2] * inv2, o[rs][nt][3] * inv2);
        }
    }
}

// ---------------------------------------------------------------------------
// Inconsistency head + pass-through copies. grid=BATCH, block=256.
// ---------------------------------------------------------------------------
__global__ void __launch_bounds__(256) inc_kernel(
    const float* __restrict__ img_sp, const float* __restrict__ txt_sp,
    const float* __restrict__ W, const float* __restrict__ bias,
    float* __restrict__ out_inc, float* __restrict__ out_img,
    float* __restrict__ out_txt)
{
    __shared__ float inc[512];
    int r = blockIdx.x;
    int j = threadIdx.x;
    float a = img_sp[r * DIM + j];
    float t = txt_sp[r * DIM + j];
    inc[j]       = a - t;
    inc[j + 256] = a * t;
    out_img[r * DIM + j] = a;
    out_txt[r * DIM + j] = t;
    __syncthreads();
    float s = bias[j];
    #pragma unroll 8
    for (int k = 0; k < 512; k++)
        s = fmaf(inc[k], W[k * DIM + j], s);
    out_inc[r * DIM + j] = s;
}

// ---------------------------------------------------------------------------
extern "C" void kernel_launch(void* const* d_in, const int* in_sizes, int n_in,
                              void* d_out, int out_size)
{
    const float* img_common = (const float*)d_in[0];
    const float* txt_common = (const float*)d_in[1];
    const float* img_sp     = (const float*)d_in[2];
    const float* txt_sp     = (const float*)d_in[3];
    const float* i2t_wq = (const float*)d_in[4];
    const float* i2t_bq = (const float*)d_in[5];
    const float* i2t_wk = (const float*)d_in[6];
    const float* i2t_bk = (const float*)d_in[7];
    const float* i2t_wv = (const float*)d_in[8];
    const float* i2t_bv = (const float*)d_in[9];
    const float* i2t_wo = (const float*)d_in[10];
    const float* i2t_bo = (const float*)d_in[11];
    const float* t2i_wq = (const float*)d_in[12];
    const float* t2i_bq = (const float*)d_in[13];
    const float* t2i_wk = (const float*)d_in[14];
    const float* t2i_bk = (const float*)d_in[15];
    const float* t2i_wv = (const float*)d_in[16];
    const float* t2i_bv = (const float*)d_in[17];
    const float* t2i_wo = (const float*)d_in[18];
    const float* t2i_bo = (const float*)d_in[19];
    const float* ln_img_g = (const float*)d_in[20];
    const float* ln_img_b = (const float*)d_in[21];
    const float* ln_txt_g = (const float*)d_in[22];
    const float* ln_txt_b = (const float*)d_in[23];
    const float* enh_w = (const float*)d_in[24];
    const float* enh_b = (const float*)d_in[25];
    const float* inc_w = (const float*)d_in[26];
    const float* inc_b = (const float*)d_in[27];

    float* out = (float*)d_out;
    float* out_enh = out;
    float* out_inc = out + BUFSZ;
    float* out_img = out + BUFSZ + 4096;
    float* out_txt = out + BUFSZ + 8192;

    unsigned char* pool = nullptr;
    cudaGetSymbolAddress((void**)&pool, g_pool);
    __half* OutImg = (__half*)(pool + P_OUTIMG);
    __half* OutTxt = (__half*)(pool + P_OUTTXT);
    __half* AOi    = (__half*)(pool + P_AOI);
    __half* AOt    = (__half*)(pool + P_AOT);
    __half* QImg   = (__half*)(pool + P_QIMG);
    __half* QTxt   = (__half*)(pool + P_QTXT);
    __half* Wimg   = (__half*)(pool + P_WIMG);
    __half* Wtxt   = (__half*)(pool + P_WTXT);
    __half* WoI    = (__half*)(pool + P_WOI);
    __half* WoT    = (__half*)(pool + P_WOT);
    __half* Wenh   = (__half*)(pool + P_WENH);
    float*  bimg   = (float*) (pool + P_BIMG);
    float*  btxt   = (float*) (pool + P_BTXT);

    // --- inconsistency + pass-through (raw inputs only; run first)
    inc_kernel<<<BATCH, 256>>>(img_sp, txt_sp, inc_w, inc_b, out_inc, out_img, out_txt);

    // --- prep: weights only (164224 work items)
    prep_weights_kernel<<<642, 256>>>(
        i2t_wq, i2t_wk, i2t_wv, t2i_wq, t2i_wk, t2i_wv,
        i2t_bq, i2t_bk, i2t_bv, t2i_bq, t2i_bk, t2i_bv,
        i2t_wo, t2i_wo, enh_w,
        Wimg, Wtxt, WoI, WoT, Wenh, bimg, btxt);

    // --- fused QKV GEMMs reading FP32 activations directly
    dim3 gq(768 / 128, MROWS / 128, 2);   // (6, 128, 2)
    gemm_f32a_dual<<<gq, 256>>>(
        img_common, Wimg, bimg, OutImg,
        txt_common, Wtxt, btxt, OutTxt,
        768, 768, DIM);

    // --- attention, both directions in one launch
    dim3 ga(SEQ / 256, NHEADS, 2 * BATCH);
    attn_f16<<<ga, 256>>>(OutImg, OutTxt, AOi, AOt);

    // --- fused O-proj + residual(fp32) + LayerNorm
    dim3 go(MROWS / 64, 2);               // (256, 2)
    oproj_ln_dual<<<go, 256>>>(
        AOi, WoI, i2t_bo, img_common, ln_img_g, ln_img_b, QImg,
        AOt, WoT, t2i_bo, txt_common, ln_txt_g, ln_txt_b, QTxt);

    // --- enhancement: concat [16384,512] @ [512,256] -> fp32 out
    dim3 ge(DIM / 128, MROWS / 128, 1);   // (2, 128, 1)
    gemm_f16_dual<0><<<ge, 256>>>(
        QImg, QTxt, Wenh, enh_b, out_enh,
        QImg, QTxt, Wenh, enh_b, out_enh,
        DIM, DIM, DIM, 2 * DIM);
}

// round 15
// speedup vs baseline: 1.0063x; 1.0063x over previous
#include <cuda_runtime.h>
#include <cuda_fp16.h>
#include <math.h>

#define DIM     256
#define SEQ     1024
#define BATCH   16
#define NHEADS  8
#define HDIM    32
#define MROWS   (BATCH * SEQ)          /* 16384 */
#define BUFSZ   ((size_t)MROWS * DIM)  /* 4194304 elements */

// ---------------------------------------------------------------------------
// scratch pool (bytes)
// ---------------------------------------------------------------------------
#define P_IMG_H   (0ull)
#define P_TXT_H   (P_IMG_H  + 8388608ull)
#define P_OUTIMG  (P_TXT_H  + 8388608ull)
#define P_OUTTXT  (P_OUTIMG + 25165824ull)
#define P_AOI     (P_OUTTXT + 25165824ull)
#define P_AOT     (P_AOI    + 8388608ull)
#define P_QIMG    (P_AOT    + 8388608ull)
#define P_QTXT    (P_QIMG   + 8388608ull)
#define P_WIMG    (P_QTXT   + 8388608ull)
#define P_WTXT    (P_WIMG   + 393216ull)
#define P_WOI     (P_WTXT   + 393216ull)
#define P_WOT     (P_WOI    + 131072ull)
#define P_WENH    (P_WOT    + 131072ull)
#define P_BIMG    (P_WENH   + 262144ull)
#define P_BTXT    (P_BIMG   + 4096ull)
#define P_END     (P_BTXT   + 4096ull)

__device__ __align__(256) unsigned char g_pool[P_END];

// ---------------------------------------------------------------------------
// helpers
// ---------------------------------------------------------------------------
__device__ __forceinline__ unsigned f2h2(float lo, float hi) {
    unsigned u;
    asm("cvt.rn.f16x2.f32 %0, %1, %2;" : "=r"(u) : "f"(hi), "f"(lo));
    return u;
}
__device__ __forceinline__ unsigned h2ex2(unsigned x) {
    unsigned r;
    asm("ex2.approx.f16x2 %0, %1;" : "=r"(r) : "r"(x));
    return r;
}
__device__ __forceinline__ void mma_f16(
    float& c0, float& c1, float& c2, float& c3,
    unsigned a0, unsigned a1, unsigned a2, unsigned a3,
    unsigned b0, unsigned b1)
{
    asm volatile(
        "mma.sync.aligned.m16n8k16.row.col.f32.f16.f16.f32 "
        "{%0,%1,%2,%3}, {%4,%5,%6,%7}, {%8,%9}, {%0,%1,%2,%3};"
        : "+f"(c0), "+f"(c1), "+f"(c2), "+f"(c3)
        : "r"(a0), "r"(a1), "r"(a2), "r"(a3), "r"(b0), "r"(b1));
}
__device__ __forceinline__ void ldsm_x4(
    unsigned& r0, unsigned& r1, unsigned& r2, unsigned& r3, unsigned addr)
{
    asm volatile("ldmatrix.sync.aligned.m8n8.x4.shared.b16 {%0,%1,%2,%3}, [%4];"
        : "=r"(r0), "=r"(r1), "=r"(r2), "=r"(r3) : "r"(addr));
}
__device__ __forceinline__ void ldsm_x4_t(
    unsigned& r0, unsigned& r1, unsigned& r2, unsigned& r3, unsigned addr)
{
    asm volatile("ldmatrix.sync.aligned.m8n8.x4.trans.shared.b16 {%0,%1,%2,%3}, [%4];"
        : "=r"(r0), "=r"(r1), "=r"(r2), "=r"(r3) : "r"(addr));
}
__device__ __forceinline__ unsigned smem_u32(const void* p) {
    return (unsigned)__cvta_generic_to_shared(p);
}
__device__ __forceinline__ void cp16(unsigned dst, const void* src) {
    asm volatile("cp.async.cg.shared.global [%0], [%1], 16;" :: "r"(dst), "l"(src));
}
__device__ __forceinline__ void cp_commit() { asm volatile("cp.async.commit_group;"); }
__device__ __forceinline__ void cp_wait0()  { asm volatile("cp.async.wait_group 0;"); }
__device__ __forceinline__ void cp_wait1()  { asm volatile("cp.async.wait_group 1;"); }

// ---------------------------------------------------------------------------
// prep: activations f2h + all weight packing in ONE launch (R12 layout).
// ---------------------------------------------------------------------------
__global__ void prep_all_kernel(
    const float* __restrict__ img, __half* __restrict__ img_h,
    const float* __restrict__ txt, __half* __restrict__ txt_h,
    const float* __restrict__ i2t_wq, const float* __restrict__ i2t_wk,
    const float* __restrict__ i2t_wv, const float* __restrict__ t2i_wq,
    const float* __restrict__ t2i_wk, const float* __restrict__ t2i_wv,
    const float* __restrict__ i2t_bq, const float* __restrict__ i2t_bk,
    const float* __restrict__ i2t_bv, const float* __restrict__ t2i_bq,
    const float* __restrict__ t2i_bk, const float* __restrict__ t2i_bv,
    const float* __restrict__ i2t_wo, const float* __restrict__ t2i_wo,
    const float* __restrict__ enh_w,
    __half* __restrict__ Wimg, __half* __restrict__ Wtxt,
    __half* __restrict__ WoI,  __half* __restrict__ WoT,
    __half* __restrict__ Wenh,
    float* __restrict__ bimg, float* __restrict__ btxt)
{
    int i = blockIdx.x * blockDim.x + threadIdx.x;
    if (i < 2097152) {
        const float* s; __half* d; int j;
        if (i < 1048576) { s = img; d = img_h; j = i; }
        else             { s = txt; d = txt_h; j = i - 1048576; }
        float4 v = ((const float4*)s)[j];
        uint2 u;
        u.x = f2h2(v.x, v.y);
        u.y = f2h2(v.z, v.w);
        ((uint2*)d)[j] = u;
        return;
    }
    int w = i - 2097152;
    if (w < 98304) {
        int pick = (w >= 49152);
        int g = pick ? w - 49152 : w;
        const float* w0 = pick ? t2i_wq : i2t_wq;
        const float* w1 = pick ? i2t_wk : t2i_wk;
        const float* w2 = pick ? i2t_wv : t2i_wv;
        __half* Wd = pick ? Wtxt : Wimg;
        int k = g / 192, jj = (g % 192) * 4;
        const float* src = (jj < 256) ? w0 : (jj < 512) ? w1 : w2;
        float4 v = *(const float4*)(src + k * 256 + (jj & 255));
        uint2 u;
        u.x = f2h2(v.x, v.y);
        u.y = f2h2(v.z, v.w);
        *(uint2*)(Wd + k * 768 + jj) = u;
    } else if (w < 163872) {
        int j = w - 98304;
        const float* s; __half* d;
        if (j < 16384)      { s = i2t_wo; d = WoI; }
        else if (j < 32768) { s = t2i_wo; d = WoT; j -= 16384; }
        else                { s = enh_w;  d = Wenh; j -= 32768; }
        if (j < 32768) {
            float4 v = ((const float4*)s)[j];
            uint2 u;
            u.x = f2h2(v.x, v.y);
            u.y = f2h2(v.z, v.w);
            ((uint2*)d)[j] = u;
        }
    } else if (w < 164256) {
        int pick = (w >= 164064);
        int g = pick ? w - 164064 : w - 163872;    // 0..191
        const float* b0 = pick ? t2i_bq : i2t_bq;
        const float* b1 = pick ? i2t_bk : t2i_bk;
        const float* b2 = pick ? i2t_bv : t2i_bv;
        float* bd = pick ? btxt : bimg;
        int j4 = g * 4;
        const float* src = (j4 < 256) ? b0 : (j4 < 512) ? b1 : b2;
        *(float4*)(bd + j4) = *(const float4*)(src + (j4 & 255));
    }
}

// ---------------------------------------------------------------------------
// FP16 GEMM, dual-problem (R10, frozen): 128x128x32 block tile.
// ---------------------------------------------------------------------------
#define AST 40
#define BST 136
#define ABUF (128 * AST)
#define BBUF (32 * BST)

template<int OUT_HALF>
__global__ void __launch_bounds__(256, 2) gemm_f16_dual(
    const __half* A1_0, const __half* A2_0, const __half* W_0,
    const float* b_0, void* C_0,
    const __half* A1_1, const __half* A2_1, const __half* W_1,
    const float* b_1, void* C_1,
    int ksplit, int ldc, int N, int K)
{
    __shared__ __align__(16) __half As[2 * ABUF];
    __shared__ __align__(16) __half Bs[2 * BBUF];

    int zz = blockIdx.z;
    const __half* A1 = zz ? A1_1 : A1_0;
    const __half* A2 = zz ? A2_1 : A2_0;
    const __half* W  = zz ? W_1  : W_0;
    const float* bias = zz ? b_1 : b_0;
    void* Cv = zz ? C_1 : C_0;

    int tid = threadIdx.x, lane = tid & 31, warp = tid >> 5;
    int wm = warp & 3, wn = warp >> 2;
    int gid = lane >> 2, tig = lane & 3;
    int m0 = blockIdx.y * 128, n0 = blockIdx.x * 128;

    int ar0 = tid >> 2, ac = (tid & 3) * 8;
    int br = tid >> 4,  bc = (tid & 15) * 8;

    unsigned As_b = smem_u32(As), Bs_b = smem_u32(Bs);

    int t3 = lane >> 3, lr = lane & 7, tq = t3 & 1, th = t3 >> 1;
    unsigned a_ln = (unsigned)(((wm * 32 + tq * 8 + lr) * AST + th * 8) * 2);
    unsigned b_ln = (unsigned)(((tq * 8 + lr) * BST + wn * 64 + th * 8) * 2);

    float acc[2][8][4] = {};

    auto issue = [&](int buf, int k0) {
        const __half* Ah = (k0 < ksplit) ? (A1 + k0) : (A2 + (k0 - ksplit));
        unsigned ad = As_b + (unsigned)(buf * ABUF * 2);
        cp16(ad + (unsigned)((ar0 * AST + ac) * 2),
             Ah + (size_t)(m0 + ar0) * DIM + ac);
        cp16(ad + (unsigned)(((ar0 + 64) * AST + ac) * 2),
             Ah + (size_t)(m0 + ar0 + 64) * DIM + ac);
        unsigned bd = Bs_b + (unsigned)(buf * BBUF * 2);
        cp16(bd + (unsigned)((br * BST + bc) * 2),
             W + (size_t)(k0 + br) * N + n0 + bc);
        cp16(bd + (unsigned)(((br + 16) * BST + bc) * 2),
             W + (size_t)(k0 + br + 16) * N + n0 + bc);
    };

    int T = K / 32;
    issue(0, 0);
    cp_commit();

    for (int it = 0; it < T; it++) {
        if (it + 1 < T) {
            issue((it + 1) & 1, (it + 1) * 32);
            cp_commit();
            cp_wait1();
        } else {
            cp_wait0();
        }
        __syncthreads();

        unsigned ab = As_b + (unsigned)((it & 1) * ABUF * 2) + a_ln;
        unsigned bb = Bs_b + (unsigned)((it & 1) * BBUF * 2) + b_ln;
        #pragma unroll
        for (int kk = 0; kk < 2; kk++) {
            unsigned af[2][4];
            ldsm_x4(af[0][0], af[0][1], af[0][2], af[0][3], ab + kk * 32);
            ldsm_x4(af[1][0], af[1][1], af[1][2], af[1][3],
                    ab + 16 * AST * 2 + kk * 32);
            unsigned bf[8][2];
            #pragma unroll
            for (int bq = 0; bq < 4; bq++) {
                unsigned r0, r1, r2, r3;
                ldsm_x4_t(r0, r1, r2, r3,
                          bb + (unsigned)(kk * (16 * BST * 2) + bq * 32));
                bf[bq*2][0]   = r0; bf[bq*2][1]   = r1;
                bf[bq*2+1][0] = r2; bf[bq*2+1][1] = r3;
            }
            #pragma unroll
            for (int mt = 0; mt < 2; mt++)
                #pragma unroll
                for (int nt = 0; nt < 8; nt++)
                    mma_f16(acc[mt][nt][0], acc[mt][nt][1],
                            acc[mt][nt][2], acc[mt][nt][3],
                            af[mt][0], af[mt][1], af[mt][2], af[mt][3],
                            bf[nt][0], bf[nt][1]);
        }
        __syncthreads();
    }

    #pragma unroll
    for (int mt = 0; mt < 2; mt++) {
        #pragma unroll
        for (int nt = 0; nt < 8; nt++) {
            int r = m0 + wm * 32 + mt * 16 + gid;
            int c = n0 + wn * 64 + nt * 8 + tig * 2;
            float b0 = bias[c], b1 = bias[c + 1];
            float x0 = acc[mt][nt][0] + b0, x1 = acc[mt][nt][1] + b1;
            float x2 = acc[mt][nt][2] + b0, x3 = acc[mt][nt][3] + b1;
            if (OUT_HALF) {
                __half* C = (__half*)Cv;
                *(unsigned*)&C[(size_t)r * ldc + c]       = f2h2(x0, x1);
                *(unsigned*)&C[(size_t)(r + 8) * ldc + c] = f2h2(x2, x3);
            } else {
                float* C = (float*)Cv;
                C[(size_t)r * ldc + c]           = x0;
                C[(size_t)r * ldc + c + 1]       = x1;
                C[(size_t)(r + 8) * ldc + c]     = x2;
                C[(size_t)(r + 8) * ldc + c + 1] = x3;
            }
        }
    }
}

// ---------------------------------------------------------------------------
// Fused O-projection + bias + residual(FP32) + LayerNorm + f2h (R12, frozen).
// ---------------------------------------------------------------------------
#define OAST 40
#define OBST 264
#define OABUF (64 * OAST)
#define OBBUF (32 * OBST)

__global__ void __launch_bounds__(256, 2) oproj_ln_dual(
    const __half* __restrict__ AO_0, const __half* __restrict__ Wo_0,
    const float* __restrict__ bo_0, const float* __restrict__ R_0,
    const float* __restrict__ g_0, const float* __restrict__ be_0,
    __half* __restrict__ O_0,
    const __half* __restrict__ AO_1, const __half* __restrict__ Wo_1,
    const float* __restrict__ bo_1, const float* __restrict__ R_1,
    const float* __restrict__ g_1, const float* __restrict__ be_1,
    __half* __restrict__ O_1)
{
    __shared__ __align__(16) __half As[2 * OABUF];
    __shared__ __align__(16) __half Bs[2 * OBBUF];
    __shared__ float psum[64][4];
    __shared__ float psq[64][4];
    __shared__ float murs[64][2];

    int zz = blockIdx.y;
    const __half* AO = zz ? AO_1 : AO_0;
    const __half* Wo = zz ? Wo_1 : Wo_0;
    const float* bo  = zz ? bo_1 : bo_0;
    const float* R   = zz ? R_1  : R_0;
    const float* gam = zz ? g_1  : g_0;
    const float* bet = zz ? be_1 : be_0;
    __half* O = zz ? O_1 : O_0;

    int tid = threadIdx.x, lane = tid & 31, warp = tid >> 5;
    int wm = warp & 1, wn = warp >> 1;
    int gid = lane >> 2, tig = lane & 3;
    int m0 = blockIdx.x * 64;

    int ar0 = tid >> 2, ac = (tid & 3) * 8;
    int br  = tid >> 5, bc = (tid & 31) * 8;

    unsigned As_b = smem_u32(As), Bs_b = smem_u32(Bs);

    int t3 = lane >> 3, lr = lane & 7, tq = t3 & 1, th = t3 >> 1;
    unsigned a_ln = (unsigned)(((wm * 32 + tq * 8 + lr) * OAST + th * 8) * 2);
    unsigned b_ln = (unsigned)(((tq * 8 + lr) * OBST + wn * 64 + th * 8) * 2);

    float acc[2][8][4] = {};

    auto issue = [&](int buf, int k0) {
        unsigned ad = As_b + (unsigned)(buf * OABUF * 2);
        cp16(ad + (unsigned)((ar0 * OAST + ac) * 2),
             AO + (size_t)(m0 + ar0) * DIM + k0 + ac);
        unsigned bd = Bs_b + (unsigned)(buf * OBBUF * 2);
        #pragma unroll
        for (int i = 0; i < 4; i++)
            cp16(bd + (unsigned)(((br + i * 8) * OBST + bc) * 2),
                 Wo + (size_t)(k0 + br + i * 8) * DIM + bc);
    };

    const int T = DIM / 32;
    issue(0, 0);
    cp_commit();

    for (int it = 0; it < T; it++) {
        if (it + 1 < T) {
            issue((it + 1) & 1, (it + 1) * 32);
            cp_commit();
            cp_wait1();
        } else {
            cp_wait0();
        }
        __syncthreads();

        unsigned ab = As_b + (unsigned)((it & 1) * OABUF * 2) + a_ln;
        unsigned bb = Bs_b + (unsigned)((it & 1) * OBBUF * 2) + b_ln;
        #pragma unroll
        for (int kk = 0; kk < 2; kk++) {
            unsigned af[2][4];
            ldsm_x4(af[0][0], af[0][1], af[0][2], af[0][3], ab + kk * 32);
            ldsm_x4(af[1][0], af[1][1], af[1][2], af[1][3],
                    ab + 16 * OAST * 2 + kk * 32);
            unsigned bf[8][2];
            #pragma unroll
            for (int bq = 0; bq < 4; bq++) {
                unsigned r0, r1, r2, r3;
                ldsm_x4_t(r0, r1, r2, r3,
                          bb + (unsigned)(kk * (16 * OBST * 2) + bq * 32));
                bf[bq*2][0]   = r0; bf[bq*2][1]   = r1;
                bf[bq*2+1][0] = r2; bf[bq*2+1][1] = r3;
            }
            #pragma unroll
            for (int mt = 0; mt < 2; mt++)
                #pragma unroll
                for (int nt = 0; nt < 8; nt++)
                    mma_f16(acc[mt][nt][0], acc[mt][nt][1],
                            acc[mt][nt][2], acc[mt][nt][3],
                            af[mt][0], af[mt][1], af[mt][2], af[mt][3],
                            bf[nt][0], bf[nt][1]);
        }
        __syncthreads();
    }

    #pragma unroll
    for (int mt = 0; mt < 2; mt++) {
        int r1 = m0 + wm * 32 + mt * 16 + gid;
        float s1 = 0.f, q1 = 0.f, s2 = 0.f, q2 = 0.f;
        #pragma unroll
        for (int nt = 0; nt < 8; nt++) {
            int c = wn * 64 + nt * 8 + tig * 2;
            float b0 = bo[c], b1 = bo[c + 1];
            float2 rv1 = *(const float2*)&R[(size_t)r1 * DIM + c];
            float2 rv2 = *(const float2*)&R[(size_t)(r1 + 8) * DIM + c];
            float x0 = acc[mt][nt][0] + b0 + rv1.x;
            float x1 = acc[mt][nt][1] + b1 + rv1.y;
            float x2 = acc[mt][nt][2] + b0 + rv2.x;
            float x3 = acc[mt][nt][3] + b1 + rv2.y;
            acc[mt][nt][0] = x0; acc[mt][nt][1] = x1;
            acc[mt][nt][2] = x2; acc[mt][nt][3] = x3;
            s1 += x0 + x1;
            q1 = fmaf(x0, x0, q1); q1 = fmaf(x1, x1, q1);
            s2 += x2 + x3;
            q2 = fmaf(x2, x2, q2); q2 = fmaf(x3, x3, q2);
        }
        #pragma unroll
        for (int off = 1; off <= 2; off <<= 1) {
            s1 += __shfl_xor_sync(0xFFFFFFFFu, s1, off);
            q1 += __shfl_xor_sync(0xFFFFFFFFu, q1, off);
            s2 += __shfl_xor_sync(0xFFFFFFFFu, s2, off);
            q2 += __shfl_xor_sync(0xFFFFFFFFu, q2, off);
        }
        if (tig == 0) {
            int rl = wm * 32 + mt * 16 + gid;
            psum[rl][wn] = s1;  psq[rl][wn] = q1;
            psum[rl + 8][wn] = s2;  psq[rl + 8][wn] = q2;
        }
    }
    __syncthreads();

    if (tid < 64) {
        float ss = psum[tid][0] + psum[tid][1] + psum[tid][2] + psum[tid][3];
        float qq = psq[tid][0] + psq[tid][1] + psq[tid][2] + psq[tid][3];
        float mu = ss * (1.f / 256.f);
        float var = qq * (1.f / 256.f) - mu * mu;
        murs[tid][0] = mu;
        murs[tid][1] = rsqrtf(var + 1e-5f);
    }
    __syncthreads();

    #pragma unroll
    for (int mt = 0; mt < 2; mt++) {
        int rl = wm * 32 + mt * 16 + gid;
        float mu1 = murs[rl][0],     rs1 = murs[rl][1];
        float mu2 = murs[rl + 8][0], rs2 = murs[rl + 8][1];
        int r1 = m0 + rl;
        #pragma unroll
        for (int nt = 0; nt < 8; nt++) {
            int c = wn * 64 + nt * 8 + tig * 2;
            float g0 = gam[c], g1 = gam[c + 1];
            float e0 = bet[c], e1 = bet[c + 1];
            *(unsigned*)&O[(size_t)r1 * DIM + c] =
                f2h2((acc[mt][nt][0] - mu1) * rs1 * g0 + e0,
                     (acc[mt][nt][1] - mu1) * rs1 * g1 + e1);
            *(unsigned*)&O[(size_t)(r1 + 8) * DIM + c] =
                f2h2((acc[mt][nt][2] - mu2) * rs2 * g0 + e0,
                     (acc[mt][nt][3] - mu2) * rs2 * g1 + e1);
        }
    }
}

// ---------------------------------------------------------------------------
// FP16 flash attention v5: fused per-16-key pipeline (R11 structure, low regs)
// + tensor-core ones-mma row sums (R9 reduction, no scalar work).
// grid = (SEQ/256, NHEADS, 2*BATCH), block 256, target 3 blocks/SM.
// ---------------------------------------------------------------------------
#define KST 40
#define KVBUF (64 * KST)

__global__ void __launch_bounds__(256, 3) attn_f16(
    const __half* __restrict__ OutImg, const __half* __restrict__ OutTxt,
    __half* __restrict__ AOi, __half* __restrict__ AOt)
{
    __shared__ __align__(16) __half Ks[2 * KVBUF];
    __shared__ __align__(16) __half Vs[2 * KVBUF];

    int tid = threadIdx.x, lane = tid & 31, warp = tid >> 5;
    int gid = lane >> 2, tig = lane & 3;
    int zz = blockIdx.z;
    int dir = zz >> 4, b = zz & 15;
    const __half* Q  = dir ? OutTxt : OutImg;
    const __half* Kp = (dir ? OutImg : OutTxt) + 256;
    const __half* Vp = (dir ? OutImg : OutTxt) + 512;
    __half* O = dir ? AOt : AOi;
    const int ldin = 768;

    int h = blockIdx.y;
    int q0 = blockIdx.x * 256 + warp * 32;
    int hoff = h * HDIM;
    size_t rowQ = (size_t)b * SEQ + q0;

    int s_row = tid >> 2, s_c = (tid & 3) * 8;

    unsigned Ks_b = smem_u32(Ks), Vs_b = smem_u32(Vs);

    int t3 = lane >> 3, lr = lane & 7, tq = t3 & 1, th = t3 >> 1;
    unsigned kv_ln = (unsigned)(((tq * 8 + lr) * KST + th * 8) * 2);

    // persistent Q fragments, pre-scaled by log2(e)/sqrt(32)
    const __half2 c2h = __float2half2_rn(0.25503526f);
    unsigned qf[2][2][4];
    #pragma unroll
    for (int rs = 0; rs < 2; rs++) {
        #pragma unroll
        for (int kk = 0; kk < 2; kk++) {
            const __half* q1 = Q + (rowQ + rs * 16 + gid) * ldin + hoff + kk * 16 + tig * 2;
            const __half* q2 = q1 + 8 * ldin;
            __half2 v;
            v = __hmul2(*(const __half2*)q1,       c2h); qf[rs][kk][0] = *(unsigned*)&v;
            v = __hmul2(*(const __half2*)q2,       c2h); qf[rs][kk][1] = *(unsigned*)&v;
            v = __hmul2(*(const __half2*)(q1 + 8), c2h); qf[rs][kk][2] = *(unsigned*)&v;
            v = __hmul2(*(const __half2*)(q2 + 8), c2h); qf[rs][kk][3] = *(unsigned*)&v;
        }
    }

    const unsigned ONES = 0x3C003C00u;
    float o[2][4][4] = {};
    float ol[2][4] = {};

    auto issue = [&](int buf, int kt) {
        size_t g = ((size_t)b * SEQ + kt + s_row) * ldin + hoff + s_c;
        unsigned off = (unsigned)(buf * KVBUF * 2) + (unsigned)((s_row * KST + s_c) * 2);
        cp16(Ks_b + off, Kp + g);
        cp16(Vs_b + off, Vp + g);
    };

    issue(0, 0);
    cp_commit();

    const int T = SEQ / 64;
    for (int it = 0; it < T; it++) {
        if (it + 1 < T) {
            issue((it + 1) & 1, (it + 1) * 64);
            cp_commit();
            cp_wait1();
        } else {
            cp_wait0();
        }
        __syncthreads();

        unsigned kb = Ks_b + (unsigned)((it & 1) * KVBUF * 2) + kv_ln;
        unsigned vb = Vs_b + (unsigned)((it & 1) * KVBUF * 2) + kv_ln;

        #pragma unroll
        for (int kg = 0; kg < 4; kg++) {        // fused 16-key pipeline
            unsigned ka0, ka1, ka2, ka3, kc0, kc1, kc2, kc3;
            ldsm_x4(ka0, ka1, ka2, ka3, kb + (unsigned)((kg * 16 * KST) * 2));
            ldsm_x4(kc0, kc1, kc2, kc3, kb + (unsigned)((kg * 16 * KST + 16) * 2));

            float s0[2][4] = {}, s1[2][4] = {};
            mma_f16(s0[0][0], s0[0][1], s0[0][2], s0[0][3],
                    qf[0][0][0], qf[0][0][1], qf[0][0][2], qf[0][0][3], ka0, ka2);
            mma_f16(s0[0][0], s0[0][1], s0[0][2], s0[0][3],
                    qf[0][1][0], qf[0][1][1], qf[0][1][2], qf[0][1][3], kc0, kc2);
            mma_f16(s0[1][0], s0[1][1], s0[1][2], s0[1][3],
                    qf[0][0][0], qf[0][0][1], qf[0][0][2], qf[0][0][3], ka1, ka3);
            mma_f16(s0[1][0], s0[1][1], s0[1][2], s0[1][3],
                    qf[0][1][0], qf[0][1][1], qf[0][1][2], qf[0][1][3], kc1, kc3);
            mma_f16(s1[0][0], s1[0][1], s1[0][2], s1[0][3],
                    qf[1][0][0], qf[1][0][1], qf[1][0][2], qf[1][0][3], ka0, ka2);
            mma_f16(s1[0][0], s1[0][1], s1[0][2], s1[0][3],
                    qf[1][1][0], qf[1][1][1], qf[1][1][2], qf[1][1][3], kc0, kc2);
            mma_f16(s1[1][0], s1[1][1], s1[1][2], s1[1][3],
                    qf[1][0][0], qf[1][0][1], qf[1][0][2], qf[1][0][3], ka1, ka3);
            mma_f16(s1[1][0], s1[1][1], s1[1][2], s1[1][3],
                    qf[1][1][0], qf[1][1][1], qf[1][1][2], qf[1][1][3], kc1, kc3);

            unsigned p0[4], p1[4];
            p0[0] = h2ex2(f2h2(s0[0][0], s0[0][1]));
            p0[1] = h2ex2(f2h2(s0[0][2], s0[0][3]));
            p0[2] = h2ex2(f2h2(s0[1][0], s0[1][1]));
            p0[3] = h2ex2(f2h2(s0[1][2], s0[1][3]));
            p1[0] = h2ex2(f2h2(s1[0][0], s1[0][1]));
            p1[1] = h2ex2(f2h2(s1[0][2], s1[0][3]));
            p1[2] = h2ex2(f2h2(s1[1][0], s1[1][1]));
            p1[3] = h2ex2(f2h2(s1[1][2], s1[1][3]));

            // tensor-core row sums (exact, no scalar reduction work)
            mma_f16(ol[0][0], ol[0][1], ol[0][2], ol[0][3],
                    p0[0], p0[1], p0[2], p0[3], ONES, ONES);
            mma_f16(ol[1][0], ol[1][1], ol[1][2], ol[1][3],
                    p1[0], p1[1], p1[2], p1[3], ONES, ONES);

            unsigned v0, v1, v2, v3, w0, w1, w2, w3;
            ldsm_x4_t(v0, v1, v2, v3, vb + (unsigned)((kg * 16 * KST) * 2));
            ldsm_x4_t(w0, w1, w2, w3, vb + (unsigned)((kg * 16 * KST + 16) * 2));
            mma_f16(o[0][0][0], o[0][0][1], o[0][0][2], o[0][0][3],
                    p0[0], p0[1], p0[2], p0[3], v0, v1);
            mma_f16(o[0][1][0], o[0][1][1], o[0][1][2], o[0][1][3],
                    p0[0], p0[1], p0[2], p0[3], v2, v3);
            mma_f16(o[0][2][0], o[0][2][1], o[0][2][2], o[0][2][3],
                    p0[0], p0[1], p0[2], p0[3], w0, w1);
            mma_f16(o[0][3][0], o[0][3][1], o[0][3][2], o[0][3][3],
                    p0[0], p0[1], p0[2], p0[3], w2, w3);
            mma_f16(o[1][0][0], o[1][0][1], o[1][0][2], o[1][0][3],
                    p1[0], p1[1], p1[2], p1[3], v0, v1);
            mma_f16(o[1][1][0], o[1][1][1], o[1][1][2], o[1][1][3],
                    p1[0], p1[1], p1[2], p1[3], v2, v3);
            mma_f16(o[1][2][0], o[1][2][1], o[1][2][2], o[1][2][3],
                    p1[0], p1[1], p1[2], p1[3], w0, w1);
            mma_f16(o[1][3][0], o[1][3][1], o[1][3][2], o[1][3][3],
                    p1[0], p1[1], p1[2], p1[3], w2, w3);
        }
        __syncthreads();
    }

    #pragma unroll
    for (int rs = 0; rs < 2; rs++) {
        float inv1 = 1.f / ol[rs][0];
        float inv2 = 1.f / ol[rs][2];
        size_t r1 = rowQ + rs * 16 + gid;
        #pragma unroll
        for (int nt = 0; nt < 4; nt++) {
            int col = hoff + nt * 8 + tig * 2;
            *(unsigned*)&O[r1 * DIM + col] =
                f2h2(o[rs][nt][0] * inv1, o[rs][nt][1] * inv1);
            *(unsigned*)&O[(r1 + 8) * DIM + col] =
                f2h2(o[rs][nt][2] * inv2, o[rs][nt][3] * inv2);
        }
    }
}

// ---------------------------------------------------------------------------
// Inconsistency head + pass-through copies. grid=BATCH, block=256.
// ---------------------------------------------------------------------------
__global__ void __launch_bounds__(256) inc_kernel(
    const float* __restrict__ img_sp, const float* __restrict__ txt_sp,
    const float* __restrict__ W, const float* __restrict__ bias,
    float* __restrict__ out_inc, float* __restrict__ out_img,
    float* __restrict__ out_txt)
{
    __shared__ float inc[512];
    int r = blockIdx.x;
    int j = threadIdx.x;
    float a = img_sp[r * DIM + j];
    float t = txt_sp[r * DIM + j];
    inc[j]       = a - t;
    inc[j + 256] = a * t;
    out_img[r * DIM + j] = a;
    out_txt[r * DIM + j] = t;
    __syncthreads();
    float s = bias[j];
    #pragma unroll 8
    for (int k = 0; k < 512; k++)
        s = fmaf(inc[k], W[k * DIM + j], s);
    out_inc[r * DIM + j] = s;
}

// ---------------------------------------------------------------------------
extern "C" void kernel_launch(void* const* d_in, const int* in_sizes, int n_in,
                              void* d_out, int out_size)
{
    const float* img_common = (const float*)d_in[0];
    const float* txt_common = (const float*)d_in[1];
    const float* img_sp     = (const float*)d_in[2];
    const float* txt_sp     = (const float*)d_in[3];
    const float* i2t_wq = (const float*)d_in[4];
    const float* i2t_bq = (const float*)d_in[5];
    const float* i2t_wk = (const float*)d_in[6];
    const float* i2t_bk = (const float*)d_in[7];
    const float* i2t_wv = (const float*)d_in[8];
    const float* i2t_bv = (const float*)d_in[9];
    const float* i2t_wo = (const float*)d_in[10];
    const float* i2t_bo = (const float*)d_in[11];
    const float* t2i_wq = (const float*)d_in[12];
    const float* t2i_bq = (const float*)d_in[13];
    const float* t2i_wk = (const float*)d_in[14];
    const float* t2i_bk = (const float*)d_in[15];
    const float* t2i_wv = (const float*)d_in[16];
    const float* t2i_bv = (const float*)d_in[17];
    const float* t2i_wo = (const float*)d_in[18];
    const float* t2i_bo = (const float*)d_in[19];
    const float* ln_img_g = (const float*)d_in[20];
    const float* ln_img_b = (const float*)d_in[21];
    const float* ln_txt_g = (const float*)d_in[22];
    const float* ln_txt_b = (const float*)d_in[23];
    const float* enh_w = (const float*)d_in[24];
    const float* enh_b = (const float*)d_in[25];
    const float* inc_w = (const float*)d_in[26];
    const float* inc_b = (const float*)d_in[27];

    float* out = (float*)d_out;
    float* out_enh = out;
    float* out_inc = out + BUFSZ;
    float* out_img = out + BUFSZ + 4096;
    float* out_txt = out + BUFSZ + 8192;

    unsigned char* pool = nullptr;
    cudaGetSymbolAddress((void**)&pool, g_pool);
    __half* img_h  = (__half*)(pool + P_IMG_H);
    __half* txt_h  = (__half*)(pool + P_TXT_H);
    __half* OutImg = (__half*)(pool + P_OUTIMG);
    __half* OutTxt = (__half*)(pool + P_OUTTXT);
    __half* AOi    = (__half*)(pool + P_AOI);
    __half* AOt    = (__half*)(pool + P_AOT);
    __half* QImg   = (__half*)(pool + P_QIMG);
    __half* QTxt   = (__half*)(pool + P_QTXT);
    __half* Wimg   = (__half*)(pool + P_WIMG);
    __half* Wtxt   = (__half*)(pool + P_WTXT);
    __half* WoI    = (__half*)(pool + P_WOI);
    __half* WoT    = (__half*)(pool + P_WOT);
    __half* Wenh   = (__half*)(pool + P_WENH);
    float*  bimg   = (float*) (pool + P_BIMG);
    float*  btxt   = (float*) (pool + P_BTXT);

    // --- prep: everything in ONE launch
    prep_all_kernel<<<8834, 256>>>(
        img_common, img_h, txt_common, txt_h,
        i2t_wq, i2t_wk, i2t_wv, t2i_wq, t2i_wk, t2i_wv,
        i2t_bq, i2t_bk, i2t_bv, t2i_bq, t2i_bk, t2i_bv,
        i2t_wo, t2i_wo, enh_w,
        Wimg, Wtxt, WoI, WoT, Wenh, bimg, btxt);

    // --- fused QKV GEMMs, both modalities in one launch (128x128 tiles)
    dim3 gq(768 / 128, MROWS / 128, 2);   // (6, 128, 2)
    gemm_f16_dual<1><<<gq, 256>>>(
        img_h, img_h, Wimg, bimg, OutImg,
        txt_h, txt_h, Wtxt, btxt, OutTxt,
        DIM, 768, 768, DIM);

    // --- attention, both directions in one launch
    dim3 ga(SEQ / 256, NHEADS, 2 * BATCH);
    attn_f16<<<ga, 256>>>(OutImg, OutTxt, AOi, AOt);

    // --- fused O-proj + residual(fp32) + LayerNorm
    dim3 go(MROWS / 64, 2);               // (256, 2)
    oproj_ln_dual<<<go, 256>>>(
        AOi, WoI, i2t_bo, img_common, ln_img_g, ln_img_b, QImg,
        AOt, WoT, t2i_bo, txt_common, ln_txt_g, ln_txt_b, QTxt);

    // --- enhancement: concat [16384,512] @ [512,256] -> fp32 out
    dim3 ge(DIM / 128, MROWS / 128, 1);   // (2, 128, 1)
    gemm_f16_dual<0><<<ge, 256>>>(
        QImg, QTxt, Wenh, enh_b, out_enh,
        QImg, QTxt, Wenh, enh_b, out_enh,
        DIM, DIM, DIM, 2 * DIM);

    // --- inconsistency + pass-through
    inc_kernel<<<BATCH, 256>>>(img_sp, txt_sp, inc_w, inc_b, out_inc, out_img, out_txt);
}

// round 16
// speedup vs baseline: 1.0315x; 1.0250x over previous
#include <cuda_runtime.h>
#include <cuda_fp16.h>
#include <math.h>

#define DIM     256
#define SEQ     1024
#define BATCH   16
#define NHEADS  8
#define HDIM    32
#define MROWS   (BATCH * SEQ)          /* 16384 */
#define BUFSZ   ((size_t)MROWS * DIM)  /* 4194304 elements */

// ---------------------------------------------------------------------------
// scratch pool (bytes)
// ---------------------------------------------------------------------------
#define P_IMG_H   (0ull)
#define P_TXT_H   (P_IMG_H  + 8388608ull)
#define P_OUTIMG  (P_TXT_H  + 8388608ull)
#define P_OUTTXT  (P_OUTIMG + 25165824ull)
#define P_AOI     (P_OUTTXT + 25165824ull)
#define P_AOT     (P_AOI    + 8388608ull)
#define P_QIMG    (P_AOT    + 8388608ull)
#define P_QTXT    (P_QIMG   + 8388608ull)
#define P_WIMG    (P_QTXT   + 8388608ull)
#define P_WTXT    (P_WIMG   + 393216ull)
#define P_WOI     (P_WTXT   + 393216ull)
#define P_WOT     (P_WOI    + 131072ull)
#define P_WENH    (P_WOT    + 131072ull)
#define P_BIMG    (P_WENH   + 262144ull)
#define P_BTXT    (P_BIMG   + 4096ull)
#define P_END     (P_BTXT   + 4096ull)

__device__ __align__(256) unsigned char g_pool[P_END];

// ---------------------------------------------------------------------------
// helpers
// ---------------------------------------------------------------------------
__device__ __forceinline__ unsigned f2h2(float lo, float hi) {
    unsigned u;
    asm("cvt.rn.f16x2.f32 %0, %1, %2;" : "=r"(u) : "f"(hi), "f"(lo));
    return u;
}
__device__ __forceinline__ unsigned h2ex2(unsigned x) {
    unsigned r;
    asm("ex2.approx.f16x2 %0, %1;" : "=r"(r) : "r"(x));
    return r;
}
__device__ __forceinline__ void mma_f16(
    float& c0, float& c1, float& c2, float& c3,
    unsigned a0, unsigned a1, unsigned a2, unsigned a3,
    unsigned b0, unsigned b1)
{
    asm volatile(
        "mma.sync.aligned.m16n8k16.row.col.f32.f16.f16.f32 "
        "{%0,%1,%2,%3}, {%4,%5,%6,%7}, {%8,%9}, {%0,%1,%2,%3};"
        : "+f"(c0), "+f"(c1), "+f"(c2), "+f"(c3)
        : "r"(a0), "r"(a1), "r"(a2), "r"(a3), "r"(b0), "r"(b1));
}
__device__ __forceinline__ void ldsm_x4(
    unsigned& r0, unsigned& r1, unsigned& r2, unsigned& r3, unsigned addr)
{
    asm volatile("ldmatrix.sync.aligned.m8n8.x4.shared.b16 {%0,%1,%2,%3}, [%4];"
        : "=r"(r0), "=r"(r1), "=r"(r2), "=r"(r3) : "r"(addr));
}
__device__ __forceinline__ void ldsm_x4_t(
    unsigned& r0, unsigned& r1, unsigned& r2, unsigned& r3, unsigned addr)
{
    asm volatile("ldmatrix.sync.aligned.m8n8.x4.trans.shared.b16 {%0,%1,%2,%3}, [%4];"
        : "=r"(r0), "=r"(r1), "=r"(r2), "=r"(r3) : "r"(addr));
}
__device__ __forceinline__ unsigned smem_u32(const void* p) {
    return (unsigned)__cvta_generic_to_shared(p);
}
__device__ __forceinline__ void cp16(unsigned dst, const void* src) {
    asm volatile("cp.async.cg.shared.global [%0], [%1], 16;" :: "r"(dst), "l"(src));
}
__device__ __forceinline__ void cp_commit() { asm volatile("cp.async.commit_group;"); }
__device__ __forceinline__ void cp_wait0()  { asm volatile("cp.async.wait_group 0;"); }
__device__ __forceinline__ void cp_wait1()  { asm volatile("cp.async.wait_group 1;"); }

// ---------------------------------------------------------------------------
// prep: activations f2h + all weight packing + inconsistency head, ONE launch.
// Blocks [0, 8834): flat conversion work (R12 layout, 2261408 items max).
// Blocks [8834, 8850): inconsistency head, r = blockIdx.x - 8834.
// ---------------------------------------------------------------------------
#define PREP_FLAT_BLOCKS 8834

__global__ void prep_all_kernel(
    const float* __restrict__ img, __half* __restrict__ img_h,
    const float* __restrict__ txt, __half* __restrict__ txt_h,
    const float* __restrict__ i2t_wq, const float* __restrict__ i2t_wk,
    const float* __restrict__ i2t_wv, const float* __restrict__ t2i_wq,
    const float* __restrict__ t2i_wk, const float* __restrict__ t2i_wv,
    const float* __restrict__ i2t_bq, const float* __restrict__ i2t_bk,
    const float* __restrict__ i2t_bv, const float* __restrict__ t2i_bq,
    const float* __restrict__ t2i_bk, const float* __restrict__ t2i_bv,
    const float* __restrict__ i2t_wo, const float* __restrict__ t2i_wo,
    const float* __restrict__ enh_w,
    __half* __restrict__ Wimg, __half* __restrict__ Wtxt,
    __half* __restrict__ WoI,  __half* __restrict__ WoT,
    __half* __restrict__ Wenh,
    float* __restrict__ bimg, float* __restrict__ btxt,
    const float* __restrict__ img_sp, const float* __restrict__ txt_sp,
    const float* __restrict__ inc_w, const float* __restrict__ inc_b,
    float* __restrict__ out_inc, float* __restrict__ out_img,
    float* __restrict__ out_txt)
{
    __shared__ float inc[512];

    if (blockIdx.x >= PREP_FLAT_BLOCKS) {
        // ----- inconsistency head block -----
        int r = blockIdx.x - PREP_FLAT_BLOCKS;
        int j = threadIdx.x;
        float a = img_sp[r * DIM + j];
        float t = txt_sp[r * DIM + j];
        inc[j]       = a - t;
        inc[j + 256] = a * t;
        out_img[r * DIM + j] = a;
        out_txt[r * DIM + j] = t;
        __syncthreads();
        float s = inc_b[j];
        #pragma unroll 8
        for (int k = 0; k < 512; k++)
            s = fmaf(inc[k], inc_w[k * DIM + j], s);
        out_inc[r * DIM + j] = s;
        return;
    }

    int i = blockIdx.x * blockDim.x + threadIdx.x;
    if (i < 2097152) {
        const float* s; __half* d; int j;
        if (i < 1048576) { s = img; d = img_h; j = i; }
        else             { s = txt; d = txt_h; j = i - 1048576; }
        float4 v = ((const float4*)s)[j];
        uint2 u;
        u.x = f2h2(v.x, v.y);
        u.y = f2h2(v.z, v.w);
        ((uint2*)d)[j] = u;
        return;
    }
    int w = i - 2097152;
    if (w < 98304) {
        int pick = (w >= 49152);
        int g = pick ? w - 49152 : w;
        const float* w0 = pick ? t2i_wq : i2t_wq;
        const float* w1 = pick ? i2t_wk : t2i_wk;
        const float* w2 = pick ? i2t_wv : t2i_wv;
        __half* Wd = pick ? Wtxt : Wimg;
        int k = g / 192, jj = (g % 192) * 4;
        const float* src = (jj < 256) ? w0 : (jj < 512) ? w1 : w2;
        float4 v = *(const float4*)(src + k * 256 + (jj & 255));
        uint2 u;
        u.x = f2h2(v.x, v.y);
        u.y = f2h2(v.z, v.w);
        *(uint2*)(Wd + k * 768 + jj) = u;
    } else if (w < 163872) {
        int j = w - 98304;
        const float* s; __half* d;
        if (j < 16384)      { s = i2t_wo; d = WoI; }
        else if (j < 32768) { s = t2i_wo; d = WoT; j -= 16384; }
        else                { s = enh_w;  d = Wenh; j -= 32768; }
        if (j < 32768) {
            float4 v = ((const float4*)s)[j];
            uint2 u;
            u.x = f2h2(v.x, v.y);
            u.y = f2h2(v.z, v.w);
            ((uint2*)d)[j] = u;
        }
    } else if (w < 164256) {
        int pick = (w >= 164064);
        int g = pick ? w - 164064 : w - 163872;    // 0..191
        const float* b0 = pick ? t2i_bq : i2t_bq;
        const float* b1 = pick ? i2t_bk : t2i_bk;
        const float* b2 = pick ? i2t_bv : t2i_bv;
        float* bd = pick ? btxt : bimg;
        int j4 = g * 4;
        const float* src = (j4 < 256) ? b0 : (j4 < 512) ? b1 : b2;
        *(float4*)(bd + j4) = *(const float4*)(src + (j4 & 255));
    }
}

// ---------------------------------------------------------------------------
// FP16 GEMM, dual-problem (R10, frozen): 128x128x32 block tile.
// ---------------------------------------------------------------------------
#define AST 40
#define BST 136
#define ABUF (128 * AST)
#define BBUF (32 * BST)

template<int OUT_HALF>
__global__ void __launch_bounds__(256, 2) gemm_f16_dual(
    const __half* A1_0, const __half* A2_0, const __half* W_0,
    const float* b_0, void* C_0,
    const __half* A1_1, const __half* A2_1, const __half* W_1,
    const float* b_1, void* C_1,
    int ksplit, int ldc, int N, int K)
{
    __shared__ __align__(16) __half As[2 * ABUF];
    __shared__ __align__(16) __half Bs[2 * BBUF];

    int zz = blockIdx.z;
    const __half* A1 = zz ? A1_1 : A1_0;
    const __half* A2 = zz ? A2_1 : A2_0;
    const __half* W  = zz ? W_1  : W_0;
    const float* bias = zz ? b_1 : b_0;
    void* Cv = zz ? C_1 : C_0;

    int tid = threadIdx.x, lane = tid & 31, warp = tid >> 5;
    int wm = warp & 3, wn = warp >> 2;
    int gid = lane >> 2, tig = lane & 3;
    int m0 = blockIdx.y * 128, n0 = blockIdx.x * 128;

    int ar0 = tid >> 2, ac = (tid & 3) * 8;
    int br = tid >> 4,  bc = (tid & 15) * 8;

    unsigned As_b = smem_u32(As), Bs_b = smem_u32(Bs);

    int t3 = lane >> 3, lr = lane & 7, tq = t3 & 1, th = t3 >> 1;
    unsigned a_ln = (unsigned)(((wm * 32 + tq * 8 + lr) * AST + th * 8) * 2);
    unsigned b_ln = (unsigned)(((tq * 8 + lr) * BST + wn * 64 + th * 8) * 2);

    float acc[2][8][4] = {};

    auto issue = [&](int buf, int k0) {
        const __half* Ah = (k0 < ksplit) ? (A1 + k0) : (A2 + (k0 - ksplit));
        unsigned ad = As_b + (unsigned)(buf * ABUF * 2);
        cp16(ad + (unsigned)((ar0 * AST + ac) * 2),
             Ah + (size_t)(m0 + ar0) * DIM + ac);
        cp16(ad + (unsigned)(((ar0 + 64) * AST + ac) * 2),
             Ah + (size_t)(m0 + ar0 + 64) * DIM + ac);
        unsigned bd = Bs_b + (unsigned)(buf * BBUF * 2);
        cp16(bd + (unsigned)((br * BST + bc) * 2),
             W + (size_t)(k0 + br) * N + n0 + bc);
        cp16(bd + (unsigned)(((br + 16) * BST + bc) * 2),
             W + (size_t)(k0 + br + 16) * N + n0 + bc);
    };

    int T = K / 32;
    issue(0, 0);
    cp_commit();

    for (int it = 0; it < T; it++) {
        if (it + 1 < T) {
            issue((it + 1) & 1, (it + 1) * 32);
            cp_commit();
            cp_wait1();
        } else {
            cp_wait0();
        }
        __syncthreads();

        unsigned ab = As_b + (unsigned)((it & 1) * ABUF * 2) + a_ln;
        unsigned bb = Bs_b + (unsigned)((it & 1) * BBUF * 2) + b_ln;
        #pragma unroll
        for (int kk = 0; kk < 2; kk++) {
            unsigned af[2][4];
            ldsm_x4(af[0][0], af[0][1], af[0][2], af[0][3], ab + kk * 32);
            ldsm_x4(af[1][0], af[1][1], af[1][2], af[1][3],
                    ab + 16 * AST * 2 + kk * 32);
            unsigned bf[8][2];
            #pragma unroll
            for (int bq = 0; bq < 4; bq++) {
                unsigned r0, r1, r2, r3;
                ldsm_x4_t(r0, r1, r2, r3,
                          bb + (unsigned)(kk * (16 * BST * 2) + bq * 32));
                bf[bq*2][0]   = r0; bf[bq*2][1]   = r1;
                bf[bq*2+1][0] = r2; bf[bq*2+1][1] = r3;
            }
            #pragma unroll
            for (int mt = 0; mt < 2; mt++)
                #pragma unroll
                for (int nt = 0; nt < 8; nt++)
                    mma_f16(acc[mt][nt][0], acc[mt][nt][1],
                            acc[mt][nt][2], acc[mt][nt][3],
                            af[mt][0], af[mt][1], af[mt][2], af[mt][3],
                            bf[nt][0], bf[nt][1]);
        }
        __syncthreads();
    }

    #pragma unroll
    for (int mt = 0; mt < 2; mt++) {
        #pragma unroll
        for (int nt = 0; nt < 8; nt++) {
            int r = m0 + wm * 32 + mt * 16 + gid;
            int c = n0 + wn * 64 + nt * 8 + tig * 2;
            float b0 = bias[c], b1 = bias[c + 1];
            float x0 = acc[mt][nt][0] + b0, x1 = acc[mt][nt][1] + b1;
            float x2 = acc[mt][nt][2] + b0, x3 = acc[mt][nt][3] + b1;
            if (OUT_HALF) {
                __half* C = (__half*)Cv;
                *(unsigned*)&C[(size_t)r * ldc + c]       = f2h2(x0, x1);
                *(unsigned*)&C[(size_t)(r + 8) * ldc + c] = f2h2(x2, x3);
            } else {
                float* C = (float*)Cv;
                C[(size_t)r * ldc + c]           = x0;
                C[(size_t)r * ldc + c + 1]       = x1;
                C[(size_t)(r + 8) * ldc + c]     = x2;
                C[(size_t)(r + 8) * ldc + c + 1] = x3;
            }
        }
    }
}

// ---------------------------------------------------------------------------
// Fused O-projection + bias + residual(FP32) + LayerNorm + f2h (R12, frozen).
// ---------------------------------------------------------------------------
#define OAST 40
#define OBST 264
#define OABUF (64 * OAST)
#define OBBUF (32 * OBST)

__global__ void __launch_bounds__(256, 2) oproj_ln_dual(
    const __half* __restrict__ AO_0, const __half* __restrict__ Wo_0,
    const float* __restrict__ bo_0, const float* __restrict__ R_0,
    const float* __restrict__ g_0, const float* __restrict__ be_0,
    __half* __restrict__ O_0,
    const __half* __restrict__ AO_1, const __half* __restrict__ Wo_1,
    const float* __restrict__ bo_1, const float* __restrict__ R_1,
    const float* __restrict__ g_1, const float* __restrict__ be_1,
    __half* __restrict__ O_1)
{
    __shared__ __align__(16) __half As[2 * OABUF];
    __shared__ __align__(16) __half Bs[2 * OBBUF];
    __shared__ float psum[64][4];
    __shared__ float psq[64][4];
    __shared__ float murs[64][2];

    int zz = blockIdx.y;
    const __half* AO = zz ? AO_1 : AO_0;
    const __half* Wo = zz ? Wo_1 : Wo_0;
    const float* bo  = zz ? bo_1 : bo_0;
    const float* R   = zz ? R_1  : R_0;
    const float* gam = zz ? g_1  : g_0;
    const float* bet = zz ? be_1 : be_0;
    __half* O = zz ? O_1 : O_0;

    int tid = threadIdx.x, lane = tid & 31, warp = tid >> 5;
    int wm = warp & 1, wn = warp >> 1;
    int gid = lane >> 2, tig = lane & 3;
    int m0 = blockIdx.x * 64;

    int ar0 = tid >> 2, ac = (tid & 3) * 8;
    int br  = tid >> 5, bc = (tid & 31) * 8;

    unsigned As_b = smem_u32(As), Bs_b = smem_u32(Bs);

    int t3 = lane >> 3, lr = lane & 7, tq = t3 & 1, th = t3 >> 1;
    unsigned a_ln = (unsigned)(((wm * 32 + tq * 8 + lr) * OAST + th * 8) * 2);
    unsigned b_ln = (unsigned)(((tq * 8 + lr) * OBST + wn * 64 + th * 8) * 2);

    float acc[2][8][4] = {};

    auto issue = [&](int buf, int k0) {
        unsigned ad = As_b + (unsigned)(buf * OABUF * 2);
        cp16(ad + (unsigned)((ar0 * OAST + ac) * 2),
             AO + (size_t)(m0 + ar0) * DIM + k0 + ac);
        unsigned bd = Bs_b + (unsigned)(buf * OBBUF * 2);
        #pragma unroll
        for (int i = 0; i < 4; i++)
            cp16(bd + (unsigned)(((br + i * 8) * OBST + bc) * 2),
                 Wo + (size_t)(k0 + br + i * 8) * DIM + bc);
    };

    const int T = DIM / 32;
    issue(0, 0);
    cp_commit();

    for (int it = 0; it < T; it++) {
        if (it + 1 < T) {
            issue((it + 1) & 1, (it + 1) * 32);
            cp_commit();
            cp_wait1();
        } else {
            cp_wait0();
        }
        __syncthreads();

        unsigned ab = As_b + (unsigned)((it & 1) * OABUF * 2) + a_ln;
        unsigned bb = Bs_b + (unsigned)((it & 1) * OBBUF * 2) + b_ln;
        #pragma unroll
        for (int kk = 0; kk < 2; kk++) {
            unsigned af[2][4];
            ldsm_x4(af[0][0], af[0][1], af[0][2], af[0][3], ab + kk * 32);
            ldsm_x4(af[1][0], af[1][1], af[1][2], af[1][3],
                    ab + 16 * OAST * 2 + kk * 32);
            unsigned bf[8][2];
            #pragma unroll
            for (int bq = 0; bq < 4; bq++) {
                unsigned r0, r1, r2, r3;
                ldsm_x4_t(r0, r1, r2, r3,
                          bb + (unsigned)(kk * (16 * OBST * 2) + bq * 32));
                bf[bq*2][0]   = r0; bf[bq*2][1]   = r1;
                bf[bq*2+1][0] = r2; bf[bq*2+1][1] = r3;
            }
            #pragma unroll
            for (int mt = 0; mt < 2; mt++)
                #pragma unroll
                for (int nt = 0; nt < 8; nt++)
                    mma_f16(acc[mt][nt][0], acc[mt][nt][1],
                            acc[mt][nt][2], acc[mt][nt][3],
                            af[mt][0], af[mt][1], af[mt][2], af[mt][3],
                            bf[nt][0], bf[nt][1]);
        }
        __syncthreads();
    }

    #pragma unroll
    for (int mt = 0; mt < 2; mt++) {
        int r1 = m0 + wm * 32 + mt * 16 + gid;
        float s1 = 0.f, q1 = 0.f, s2 = 0.f, q2 = 0.f;
        #pragma unroll
        for (int nt = 0; nt < 8; nt++) {
            int c = wn * 64 + nt * 8 + tig * 2;
            float b0 = bo[c], b1 = bo[c + 1];
            float2 rv1 = *(const float2*)&R[(size_t)r1 * DIM + c];
            float2 rv2 = *(const float2*)&R[(size_t)(r1 + 8) * DIM + c];
            float x0 = acc[mt][nt][0] + b0 + rv1.x;
            float x1 = acc[mt][nt][1] + b1 + rv1.y;
            float x2 = acc[mt][nt][2] + b0 + rv2.x;
            float x3 = acc[mt][nt][3] + b1 + rv2.y;
            acc[mt][nt][0] = x0; acc[mt][nt][1] = x1;
            acc[mt][nt][2] = x2; acc[mt][nt][3] = x3;
            s1 += x0 + x1;
            q1 = fmaf(x0, x0, q1); q1 = fmaf(x1, x1, q1);
            s2 += x2 + x3;
            q2 = fmaf(x2, x2, q2); q2 = fmaf(x3, x3, q2);
        }
        #pragma unroll
        for (int off = 1; off <= 2; off <<= 1) {
            s1 += __shfl_xor_sync(0xFFFFFFFFu, s1, off);
            q1 += __shfl_xor_sync(0xFFFFFFFFu, q1, off);
            s2 += __shfl_xor_sync(0xFFFFFFFFu, s2, off);
            q2 += __shfl_xor_sync(0xFFFFFFFFu, q2, off);
        }
        if (tig == 0) {
            int rl = wm * 32 + mt * 16 + gid;
            psum[rl][wn] = s1;  psq[rl][wn] = q1;
            psum[rl + 8][wn] = s2;  psq[rl + 8][wn] = q2;
        }
    }
    __syncthreads();

    if (tid < 64) {
        float ss = psum[tid][0] + psum[tid][1] + psum[tid][2] + psum[tid][3];
        float qq = psq[tid][0] + psq[tid][1] + psq[tid][2] + psq[tid][3];
        float mu = ss * (1.f / 256.f);
        float var = qq * (1.f / 256.f) - mu * mu;
        murs[tid][0] = mu;
        murs[tid][1] = rsqrtf(var + 1e-5f);
    }
    __syncthreads();

    #pragma unroll
    for (int mt = 0; mt < 2; mt++) {
        int rl = wm * 32 + mt * 16 + gid;
        float mu1 = murs[rl][0],     rs1 = murs[rl][1];
        float mu2 = murs[rl + 8][0], rs2 = murs[rl + 8][1];
        int r1 = m0 + rl;
        #pragma unroll
        for (int nt = 0; nt < 8; nt++) {
            int c = wn * 64 + nt * 8 + tig * 2;
            float g0 = gam[c], g1 = gam[c + 1];
            float e0 = bet[c], e1 = bet[c + 1];
            *(unsigned*)&O[(size_t)r1 * DIM + c] =
                f2h2((acc[mt][nt][0] - mu1) * rs1 * g0 + e0,
                     (acc[mt][nt][1] - mu1) * rs1 * g1 + e1);
            *(unsigned*)&O[(size_t)(r1 + 8) * DIM + c] =
                f2h2((acc[mt][nt][2] - mu2) * rs2 * g0 + e0,
                     (acc[mt][nt][3] - mu2) * rs2 * g1 + e1);
        }
    }
}

// ---------------------------------------------------------------------------
// FP16 flash attention (R9, frozen — best measured 96.7us).
// ---------------------------------------------------------------------------
#define KST 40
#define KVBUF (64 * KST)

__global__ void __launch_bounds__(256) attn_f16(
    const __half* __restrict__ OutImg, const __half* __restrict__ OutTxt,
    __half* __restrict__ AOi, __half* __restrict__ AOt)
{
    __shared__ __align__(16) __half Ks[2 * KVBUF];
    __shared__ __align__(16) __half Vs[2 * KVBUF];

    int tid = threadIdx.x, lane = tid & 31, warp = tid >> 5;
    int gid = lane >> 2, tig = lane & 3;
    int zz = blockIdx.z;
    int dir = zz >> 4, b = zz & 15;
    const __half* Q  = dir ? OutTxt : OutImg;
    const __half* Kp = (dir ? OutImg : OutTxt) + 256;
    const __half* Vp = (dir ? OutImg : OutTxt) + 512;
    __half* O = dir ? AOt : AOi;
    const int ldin = 768;

    int h = blockIdx.y;
    int q0 = blockIdx.x * 256 + warp * 32;
    int hoff = h * HDIM;
    size_t rowQ = (size_t)b * SEQ + q0;

    int s_row = tid >> 2, s_c = (tid & 3) * 8;

    unsigned Ks_b = smem_u32(Ks), Vs_b = smem_u32(Vs);

    int t3 = lane >> 3, lr = lane & 7, tq = t3 & 1, th = t3 >> 1;
    unsigned kv_ln = (unsigned)(((tq * 8 + lr) * KST + th * 8) * 2);

    const __half2 c2h = __float2half2_rn(0.25503526f);
    unsigned qf[2][2][4];
    #pragma unroll
    for (int rs = 0; rs < 2; rs++) {
        #pragma unroll
        for (int kk = 0; kk < 2; kk++) {
            const __half* q1 = Q + (rowQ + rs * 16 + gid) * ldin + hoff + kk * 16 + tig * 2;
            const __half* q2 = q1 + 8 * ldin;
            __half2 v;
            v = __hmul2(*(const __half2*)q1,       c2h); qf[rs][kk][0] = *(unsigned*)&v;
            v = __hmul2(*(const __half2*)q2,       c2h); qf[rs][kk][1] = *(unsigned*)&v;
            v = __hmul2(*(const __half2*)(q1 + 8), c2h); qf[rs][kk][2] = *(unsigned*)&v;
            v = __hmul2(*(const __half2*)(q2 + 8), c2h); qf[rs][kk][3] = *(unsigned*)&v;
        }
    }

    const unsigned ONES = 0x3C003C00u;
    float o[2][4][4] = {};
    float ol[2][4] = {};

    auto issue = [&](int buf, int kt) {
        size_t g = ((size_t)b * SEQ + kt + s_row) * ldin + hoff + s_c;
        unsigned off = (unsigned)(buf * KVBUF * 2) + (unsigned)((s_row * KST + s_c) * 2);
        cp16(Ks_b + off, Kp + g);
        cp16(Vs_b + off, Vp + g);
    };

    issue(0, 0);
    cp_commit();

    const int T = SEQ / 64;
    for (int it = 0; it < T; it++) {
        if (it + 1 < T) {
            issue((it + 1) & 1, (it + 1) * 64);
            cp_commit();
            cp_wait1();
        } else {
            cp_wait0();
        }
        __syncthreads();

        unsigned kb = Ks_b + (unsigned)((it & 1) * KVBUF * 2) + kv_ln;
        unsigned vb = Vs_b + (unsigned)((it & 1) * KVBUF * 2) + kv_ln;

        float s0[8][4] = {}, s1[8][4] = {};
        #pragma unroll
        for (int kk = 0; kk < 2; kk++) {
            #pragma unroll
            for (int np = 0; np < 4; np++) {
                unsigned r0, r1, r2, r3;
                ldsm_x4(r0, r1, r2, r3,
                        kb + (unsigned)((np * 16 * KST + kk * 16) * 2));
                mma_f16(s0[np*2][0], s0[np*2][1], s0[np*2][2], s0[np*2][3],
                        qf[0][kk][0], qf[0][kk][1], qf[0][kk][2], qf[0][kk][3], r0, r2);
                mma_f16(s0[np*2+1][0], s0[np*2+1][1], s0[np*2+1][2], s0[np*2+1][3],
                        qf[0][kk][0], qf[0][kk][1], qf[0][kk][2], qf[0][kk][3], r1, r3);
                mma_f16(s1[np*2][0], s1[np*2][1], s1[np*2][2], s1[np*2][3],
                        qf[1][kk][0], qf[1][kk][1], qf[1][kk][2], qf[1][kk][3], r0, r2);
                mma_f16(s1[np*2+1][0], s1[np*2+1][1], s1[np*2+1][2], s1[np*2+1][3],
                        qf[1][kk][0], qf[1][kk][1], qf[1][kk][2], qf[1][kk][3], r1, r3);
            }
        }

        unsigned pa0[4][4], pa1[4][4];
        #pragma unroll
        for (int kk = 0; kk < 4; kk++) {
            pa0[kk][0] = h2ex2(f2h2(s0[2*kk][0],   s0[2*kk][1]));
            pa0[kk][1] = h2ex2(f2h2(s0[2*kk][2],   s0[2*kk][3]));
            pa0[kk][2] = h2ex2(f2h2(s0[2*kk+1][0], s0[2*kk+1][1]));
            pa0[kk][3] = h2ex2(f2h2(s0[2*kk+1][2], s0[2*kk+1][3]));
            pa1[kk][0] = h2ex2(f2h2(s1[2*kk][0],   s1[2*kk][1]));
            pa1[kk][1] = h2ex2(f2h2(s1[2*kk][2],   s1[2*kk][3]));
            pa1[kk][2] = h2ex2(f2h2(s1[2*kk+1][0], s1[2*kk+1][1]));
            pa1[kk][3] = h2ex2(f2h2(s1[2*kk+1][2], s1[2*kk+1][3]));
        }

        #pragma unroll
        for (int kk = 0; kk < 4; kk++) {
            #pragma unroll
            for (int dg = 0; dg < 2; dg++) {
                unsigned r0, r1, r2, r3;
                ldsm_x4_t(r0, r1, r2, r3,
                          vb + (unsigned)((kk * 16 * KST + dg * 16) * 2));
                mma_f16(o[0][dg*2][0], o[0][dg*2][1], o[0][dg*2][2], o[0][dg*2][3],
                        pa0[kk][0], pa0[kk][1], pa0[kk][2], pa0[kk][3], r0, r1);
                mma_f16(o[0][dg*2+1][0], o[0][dg*2+1][1], o[0][dg*2+1][2], o[0][dg*2+1][3],
                        pa0[kk][0], pa0[kk][1], pa0[kk][2], pa0[kk][3], r2, r3);
                mma_f16(o[1][dg*2][0], o[1][dg*2][1], o[1][dg*2][2], o[1][dg*2][3],
                        pa1[kk][0], pa1[kk][1], pa1[kk][2], pa1[kk][3], r0, r1);
                mma_f16(o[1][dg*2+1][0], o[1][dg*2+1][1], o[1][dg*2+1][2], o[1][dg*2+1][3],
                        pa1[kk][0], pa1[kk][1], pa1[kk][2], pa1[kk][3], r2, r3);
            }
            mma_f16(ol[0][0], ol[0][1], ol[0][2], ol[0][3],
                    pa0[kk][0], pa0[kk][1], pa0[kk][2], pa0[kk][3], ONES, ONES);
            mma_f16(ol[1][0], ol[1][1], ol[1][2], ol[1][3],
                    pa1[kk][0], pa1[kk][1], pa1[kk][2], pa1[kk][3], ONES, ONES);
        }
        __syncthreads();
    }

    #pragma unroll
    for (int rs = 0; rs < 2; rs++) {
        float inv1 = 1.f / ol[rs][0];
        float inv2 = 1.f / ol[rs][2];
        size_t r1 = rowQ + rs * 16 + gid;
        #pragma unroll
        for (int nt = 0; nt < 4; nt++) {
            int col = hoff + nt * 8 + tig * 2;
            *(unsigned*)&O[r1 * DIM + col] =
                f2h2(o[rs][nt][0] * inv1, o[rs][nt][1] * inv1);
            *(unsigned*)&O[(r1 + 8) * DIM + col] =
                f2h2(o[rs][nt][2] * inv2, o[rs][nt][3] * inv2);
        }
    }
}

// ---------------------------------------------------------------------------
extern "C" void kernel_launch(void* const* d_in, const int* in_sizes, int n_in,
                              void* d_out, int out_size)
{
    const float* img_common = (const float*)d_in[0];
    const float* txt_common = (const float*)d_in[1];
    const float* img_sp     = (const float*)d_in[2];
    const float* txt_sp     = (const float*)d_in[3];
    const float* i2t_wq = (const float*)d_in[4];
    const float* i2t_bq = (const float*)d_in[5];
    const float* i2t_wk = (const float*)d_in[6];
    const float* i2t_bk = (const float*)d_in[7];
    const float* i2t_wv = (const float*)d_in[8];
    const float* i2t_bv = (const float*)d_in[9];
    const float* i2t_wo = (const float*)d_in[10];
    const float* i2t_bo = (const float*)d_in[11];
    const float* t2i_wq = (const float*)d_in[12];
    const float* t2i_bq = (const float*)d_in[13];
    const float* t2i_wk = (const float*)d_in[14];
    const float* t2i_bk = (const float*)d_in[15];
    const float* t2i_wv = (const float*)d_in[16];
    const float* t2i_bv = (const float*)d_in[17];
    const float* t2i_wo = (const float*)d_in[18];
    const float* t2i_bo = (const float*)d_in[19];
    const float* ln_img_g = (const float*)d_in[20];
    const float* ln_img_b = (const float*)d_in[21];
    const float* ln_txt_g = (const float*)d_in[22];
    const float* ln_txt_b = (const float*)d_in[23];
    const float* enh_w = (const float*)d_in[24];
    const float* enh_b = (const float*)d_in[25];
    const float* inc_w = (const float*)d_in[26];
    const float* inc_b = (const float*)d_in[27];

    float* out = (float*)d_out;
    float* out_enh = out;
    float* out_inc = out + BUFSZ;
    float* out_img = out + BUFSZ + 4096;
    float* out_txt = out + BUFSZ + 8192;

    unsigned char* pool = nullptr;
    cudaGetSymbolAddress((void**)&pool, g_pool);
    __half* img_h  = (__half*)(pool + P_IMG_H);
    __half* txt_h  = (__half*)(pool + P_TXT_H);
    __half* OutImg = (__half*)(pool + P_OUTIMG);
    __half* OutTxt = (__half*)(pool + P_OUTTXT);
    __half* AOi    = (__half*)(pool + P_AOI);
    __half* AOt    = (__half*)(pool + P_AOT);
    __half* QImg   = (__half*)(pool + P_QIMG);
    __half* QTxt   = (__half*)(pool + P_QTXT);
    __half* Wimg   = (__half*)(pool + P_WIMG);
    __half* Wtxt   = (__half*)(pool + P_WTXT);
    __half* WoI    = (__half*)(pool + P_WOI);
    __half* WoT    = (__half*)(pool + P_WOT);
    __half* Wenh   = (__half*)(pool + P_WENH);
    float*  bimg   = (float*) (pool + P_BIMG);
    float*  btxt   = (float*) (pool + P_BTXT);

    // --- prep + inconsistency head, ONE launch (8834 flat + 16 inc blocks)
    prep_all_kernel<<<PREP_FLAT_BLOCKS + BATCH, 256>>>(
        img_common, img_h, txt_common, txt_h,
        i2t_wq, i2t_wk, i2t_wv, t2i_wq, t2i_wk, t2i_wv,
        i2t_bq, i2t_bk, i2t_bv, t2i_bq, t2i_bk, t2i_bv,
        i2t_wo, t2i_wo, enh_w,
        Wimg, Wtxt, WoI, WoT, Wenh, bimg, btxt,
        img_sp, txt_sp, inc_w, inc_b, out_inc, out_img, out_txt);

    // --- fused QKV GEMMs, both modalities in one launch (128x128 tiles)
    dim3 gq(768 / 128, MROWS / 128, 2);   // (6, 128, 2)
    gemm_f16_dual<1><<<gq, 256>>>(
        img_h, img_h, Wimg, bimg, OutImg,
        txt_h, txt_h, Wtxt, btxt, OutTxt,
        DIM, 768, 768, DIM);

    // --- attention, both directions in one launch
    dim3 ga(SEQ / 256, NHEADS, 2 * BATCH);
    attn_f16<<<ga, 256>>>(OutImg, OutTxt, AOi, AOt);

    // --- fused O-proj + residual(fp32) + LayerNorm
    dim3 go(MROWS / 64, 2);               // (256, 2)
    oproj_ln_dual<<<go, 256>>>(
        AOi, WoI, i2t_bo, img_common, ln_img_g, ln_img_b, QImg,
        AOt, WoT, t2i_bo, txt_common, ln_txt_g, ln_txt_b, QTxt);

    // --- enhancement: concat [16384,512] @ [512,256] -> fp32 out
    dim3 ge(DIM / 128, MROWS / 128, 1);   // (2, 128, 1)
    gemm_f16_dual<0><<<ge, 256>>>(
        QImg, QTxt, Wenh, enh_b, out_enh,
        QImg, QTxt, Wenh, enh_b, out_enh,
        DIM, DIM, DIM, 2 * DIM);
}

// round 17
// speedup vs baseline: 1.0394x; 1.0077x over previous
#include <cuda_runtime.h>
#include <cuda_fp16.h>
#include <math.h>

#define DIM     256
#define SEQ     1024
#define BATCH   16
#define NHEADS  8
#define HDIM    32
#define MROWS   (BATCH * SEQ)          /* 16384 */
#define BUFSZ   ((size_t)MROWS * DIM)  /* 4194304 elements */

// ---------------------------------------------------------------------------
// scratch pool (bytes)
// ---------------------------------------------------------------------------
#define P_IMG_H   (0ull)
#define P_TXT_H   (P_IMG_H  + 8388608ull)
#define P_OUTIMG  (P_TXT_H  + 8388608ull)
#define P_OUTTXT  (P_OUTIMG + 25165824ull)
#define P_AOI     (P_OUTTXT + 25165824ull)
#define P_AOT     (P_AOI    + 8388608ull)
#define P_QIMG    (P_AOT    + 8388608ull)
#define P_QTXT    (P_QIMG   + 8388608ull)
#define P_WIMG    (P_QTXT   + 8388608ull)
#define P_WTXT    (P_WIMG   + 393216ull)
#define P_WOI     (P_WTXT   + 393216ull)
#define P_WOT     (P_WOI    + 131072ull)
#define P_WENH    (P_WOT    + 131072ull)
#define P_BIMG    (P_WENH   + 262144ull)
#define P_BTXT    (P_BIMG   + 4096ull)
#define P_END     (P_BTXT   + 4096ull)

__device__ __align__(256) unsigned char g_pool[P_END];

// ---------------------------------------------------------------------------
// helpers
// ---------------------------------------------------------------------------
__device__ __forceinline__ unsigned f2h2(float lo, float hi) {
    unsigned u;
    asm("cvt.rn.f16x2.f32 %0, %1, %2;" : "=r"(u) : "f"(hi), "f"(lo));
    return u;
}
__device__ __forceinline__ unsigned h2ex2(unsigned x) {
    unsigned r;
    asm("ex2.approx.f16x2 %0, %1;" : "=r"(r) : "r"(x));
    return r;
}
__device__ __forceinline__ void mma_f16(
    float& c0, float& c1, float& c2, float& c3,
    unsigned a0, unsigned a1, unsigned a2, unsigned a3,
    unsigned b0, unsigned b1)
{
    asm volatile(
        "mma.sync.aligned.m16n8k16.row.col.f32.f16.f16.f32 "
        "{%0,%1,%2,%3}, {%4,%5,%6,%7}, {%8,%9}, {%0,%1,%2,%3};"
        : "+f"(c0), "+f"(c1), "+f"(c2), "+f"(c3)
        : "r"(a0), "r"(a1), "r"(a2), "r"(a3), "r"(b0), "r"(b1));
}
__device__ __forceinline__ void ldsm_x4(
    unsigned& r0, unsigned& r1, unsigned& r2, unsigned& r3, unsigned addr)
{
    asm volatile("ldmatrix.sync.aligned.m8n8.x4.shared.b16 {%0,%1,%2,%3}, [%4];"
        : "=r"(r0), "=r"(r1), "=r"(r2), "=r"(r3) : "r"(addr));
}
__device__ __forceinline__ void ldsm_x4_t(
    unsigned& r0, unsigned& r1, unsigned& r2, unsigned& r3, unsigned addr)
{
    asm volatile("ldmatrix.sync.aligned.m8n8.x4.trans.shared.b16 {%0,%1,%2,%3}, [%4];"
        : "=r"(r0), "=r"(r1), "=r"(r2), "=r"(r3) : "r"(addr));
}
__device__ __forceinline__ unsigned smem_u32(const void* p) {
    return (unsigned)__cvta_generic_to_shared(p);
}
__device__ __forceinline__ void cp16(unsigned dst, const void* src) {
    asm volatile("cp.async.cg.shared.global [%0], [%1], 16;" :: "r"(dst), "l"(src));
}
__device__ __forceinline__ void cp_commit() { asm volatile("cp.async.commit_group;"); }
__device__ __forceinline__ void cp_wait0()  { asm volatile("cp.async.wait_group 0;"); }
__device__ __forceinline__ void cp_wait1()  { asm volatile("cp.async.wait_group 1;"); }
__device__ __forceinline__ void cp_wait2()  { asm volatile("cp.async.wait_group 2;"); }

// ---------------------------------------------------------------------------
// prep: activations f2h + all weight packing + inconsistency head, ONE launch.
// ---------------------------------------------------------------------------
#define PREP_FLAT_BLOCKS 8834

__global__ void prep_all_kernel(
    const float* __restrict__ img, __half* __restrict__ img_h,
    const float* __restrict__ txt, __half* __restrict__ txt_h,
    const float* __restrict__ i2t_wq, const float* __restrict__ i2t_wk,
    const float* __restrict__ i2t_wv, const float* __restrict__ t2i_wq,
    const float* __restrict__ t2i_wk, const float* __restrict__ t2i_wv,
    const float* __restrict__ i2t_bq, const float* __restrict__ i2t_bk,
    const float* __restrict__ i2t_bv, const float* __restrict__ t2i_bq,
    const float* __restrict__ t2i_bk, const float* __restrict__ t2i_bv,
    const float* __restrict__ i2t_wo, const float* __restrict__ t2i_wo,
    const float* __restrict__ enh_w,
    __half* __restrict__ Wimg, __half* __restrict__ Wtxt,
    __half* __restrict__ WoI,  __half* __restrict__ WoT,
    __half* __restrict__ Wenh,
    float* __restrict__ bimg, float* __restrict__ btxt,
    const float* __restrict__ img_sp, const float* __restrict__ txt_sp,
    const float* __restrict__ inc_w, const float* __restrict__ inc_b,
    float* __restrict__ out_inc, float* __restrict__ out_img,
    float* __restrict__ out_txt)
{
    __shared__ float inc[512];

    if (blockIdx.x >= PREP_FLAT_BLOCKS) {
        int r = blockIdx.x - PREP_FLAT_BLOCKS;
        int j = threadIdx.x;
        float a = img_sp[r * DIM + j];
        float t = txt_sp[r * DIM + j];
        inc[j]       = a - t;
        inc[j + 256] = a * t;
        out_img[r * DIM + j] = a;
        out_txt[r * DIM + j] = t;
        __syncthreads();
        float s = inc_b[j];
        #pragma unroll 8
        for (int k = 0; k < 512; k++)
            s = fmaf(inc[k], inc_w[k * DIM + j], s);
        out_inc[r * DIM + j] = s;
        return;
    }

    int i = blockIdx.x * blockDim.x + threadIdx.x;
    if (i < 2097152) {
        const float* s; __half* d; int j;
        if (i < 1048576) { s = img; d = img_h; j = i; }
        else             { s = txt; d = txt_h; j = i - 1048576; }
        float4 v = ((const float4*)s)[j];
        uint2 u;
        u.x = f2h2(v.x, v.y);
        u.y = f2h2(v.z, v.w);
        ((uint2*)d)[j] = u;
        return;
    }
    int w = i - 2097152;
    if (w < 98304) {
        int pick = (w >= 49152);
        int g = pick ? w - 49152 : w;
        const float* w0 = pick ? t2i_wq : i2t_wq;
        const float* w1 = pick ? i2t_wk : t2i_wk;
        const float* w2 = pick ? i2t_wv : t2i_wv;
        __half* Wd = pick ? Wtxt : Wimg;
        int k = g / 192, jj = (g % 192) * 4;
        const float* src = (jj < 256) ? w0 : (jj < 512) ? w1 : w2;
        float4 v = *(const float4*)(src + k * 256 + (jj & 255));
        uint2 u;
        u.x = f2h2(v.x, v.y);
        u.y = f2h2(v.z, v.w);
        *(uint2*)(Wd + k * 768 + jj) = u;
    } else if (w < 163872) {
        int j = w - 98304;
        const float* s; __half* d;
        if (j < 16384)      { s = i2t_wo; d = WoI; }
        else if (j < 32768) { s = t2i_wo; d = WoT; j -= 16384; }
        else                { s = enh_w;  d = Wenh; j -= 32768; }
        if (j < 32768) {
            float4 v = ((const float4*)s)[j];
            uint2 u;
            u.x = f2h2(v.x, v.y);
            u.y = f2h2(v.z, v.w);
            ((uint2*)d)[j] = u;
        }
    } else if (w < 164256) {
        int pick = (w >= 164064);
        int g = pick ? w - 164064 : w - 163872;    // 0..191
        const float* b0 = pick ? t2i_bq : i2t_bq;
        const float* b1 = pick ? i2t_bk : t2i_bk;
        const float* b2 = pick ? i2t_bv : t2i_bv;
        float* bd = pick ? btxt : bimg;
        int j4 = g * 4;
        const float* src = (j4 < 256) ? b0 : (j4 < 512) ? b1 : b2;
        *(float4*)(bd + j4) = *(const float4*)(src + (j4 & 255));
    }
}

// ---------------------------------------------------------------------------
// FP16 GEMM, dual-problem: 128x128x32 tile, 8 warps, 3-stage cp.async pipeline.
// ---------------------------------------------------------------------------
#define AST 40
#define BST 136
#define ABUF (128 * AST)
#define BBUF (32 * BST)

template<int OUT_HALF>
__global__ void __launch_bounds__(256, 2) gemm_f16_dual(
    const __half* A1_0, const __half* A2_0, const __half* W_0,
    const float* b_0, void* C_0,
    const __half* A1_1, const __half* A2_1, const __half* W_1,
    const float* b_1, void* C_1,
    int ksplit, int ldc, int N, int K)
{
    __shared__ __align__(16) __half As[3 * ABUF];
    __shared__ __align__(16) __half Bs[3 * BBUF];

    int zz = blockIdx.z;
    const __half* A1 = zz ? A1_1 : A1_0;
    const __half* A2 = zz ? A2_1 : A2_0;
    const __half* W  = zz ? W_1  : W_0;
    const float* bias = zz ? b_1 : b_0;
    void* Cv = zz ? C_1 : C_0;

    int tid = threadIdx.x, lane = tid & 31, warp = tid >> 5;
    int wm = warp & 3, wn = warp >> 2;
    int gid = lane >> 2, tig = lane & 3;
    int m0 = blockIdx.y * 128, n0 = blockIdx.x * 128;

    int ar0 = tid >> 2, ac = (tid & 3) * 8;
    int br = tid >> 4,  bc = (tid & 15) * 8;

    unsigned As_b = smem_u32(As), Bs_b = smem_u32(Bs);

    int t3 = lane >> 3, lr = lane & 7, tq = t3 & 1, th = t3 >> 1;
    unsigned a_ln = (unsigned)(((wm * 32 + tq * 8 + lr) * AST + th * 8) * 2);
    unsigned b_ln = (unsigned)(((tq * 8 + lr) * BST + wn * 64 + th * 8) * 2);

    float acc[2][8][4] = {};

    auto issue = [&](int buf, int k0) {
        const __half* Ah = (k0 < ksplit) ? (A1 + k0) : (A2 + (k0 - ksplit));
        unsigned ad = As_b + (unsigned)(buf * ABUF * 2);
        cp16(ad + (unsigned)((ar0 * AST + ac) * 2),
             Ah + (size_t)(m0 + ar0) * DIM + ac);
        cp16(ad + (unsigned)(((ar0 + 64) * AST + ac) * 2),
             Ah + (size_t)(m0 + ar0 + 64) * DIM + ac);
        unsigned bd = Bs_b + (unsigned)(buf * BBUF * 2);
        cp16(bd + (unsigned)((br * BST + bc) * 2),
             W + (size_t)(k0 + br) * N + n0 + bc);
        cp16(bd + (unsigned)(((br + 16) * BST + bc) * 2),
             W + (size_t)(k0 + br + 16) * N + n0 + bc);
    };

    int T = K / 32;
    issue(0, 0);
    cp_commit();
    if (T > 1) { issue(1, 32); cp_commit(); }

    int buf = 0;
    for (int it = 0; it < T; it++) {
        if (it + 2 < T) {
            int nb = buf + 2; if (nb >= 3) nb -= 3;
            issue(nb, (it + 2) * 32);
            cp_commit();
            cp_wait2();
        } else if (it + 1 < T) {
            cp_wait1();
        } else {
            cp_wait0();
        }
        __syncthreads();

        unsigned ab = As_b + (unsigned)(buf * ABUF * 2) + a_ln;
        unsigned bb = Bs_b + (unsigned)(buf * BBUF * 2) + b_ln;
        #pragma unroll
        for (int kk = 0; kk < 2; kk++) {
            unsigned af[2][4];
            ldsm_x4(af[0][0], af[0][1], af[0][2], af[0][3], ab + kk * 32);
            ldsm_x4(af[1][0], af[1][1], af[1][2], af[1][3],
                    ab + 16 * AST * 2 + kk * 32);
            unsigned bf[8][2];
            #pragma unroll
            for (int bq = 0; bq < 4; bq++) {
                unsigned r0, r1, r2, r3;
                ldsm_x4_t(r0, r1, r2, r3,
                          bb + (unsigned)(kk * (16 * BST * 2) + bq * 32));
                bf[bq*2][0]   = r0; bf[bq*2][1]   = r1;
                bf[bq*2+1][0] = r2; bf[bq*2+1][1] = r3;
            }
            #pragma unroll
            for (int mt = 0; mt < 2; mt++)
                #pragma unroll
                for (int nt = 0; nt < 8; nt++)
                    mma_f16(acc[mt][nt][0], acc[mt][nt][1],
                            acc[mt][nt][2], acc[mt][nt][3],
                            af[mt][0], af[mt][1], af[mt][2], af[mt][3],
                            bf[nt][0], bf[nt][1]);
        }
        __syncthreads();
        buf++; if (buf == 3) buf = 0;
    }

    #pragma unroll
    for (int mt = 0; mt < 2; mt++) {
        #pragma unroll
        for (int nt = 0; nt < 8; nt++) {
            int r = m0 + wm * 32 + mt * 16 + gid;
            int c = n0 + wn * 64 + nt * 8 + tig * 2;
            float b0 = bias[c], b1 = bias[c + 1];
            float x0 = acc[mt][nt][0] + b0, x1 = acc[mt][nt][1] + b1;
            float x2 = acc[mt][nt][2] + b0, x3 = acc[mt][nt][3] + b1;
            if (OUT_HALF) {
                __half* C = (__half*)Cv;
                *(unsigned*)&C[(size_t)r * ldc + c]       = f2h2(x0, x1);
                *(unsigned*)&C[(size_t)(r + 8) * ldc + c] = f2h2(x2, x3);
            } else {
                float* C = (float*)Cv;
                C[(size_t)r * ldc + c]           = x0;
                C[(size_t)r * ldc + c + 1]       = x1;
                C[(size_t)(r + 8) * ldc + c]     = x2;
                C[(size_t)(r + 8) * ldc + c + 1] = x3;
            }
        }
    }
}

// ---------------------------------------------------------------------------
// Fused O-projection + bias + residual(FP32) + LayerNorm + f2h.
// 3-stage cp.async pipeline.
// ---------------------------------------------------------------------------
#define OAST 40
#define OBST 264
#define OABUF (64 * OAST)
#define OBBUF (32 * OBST)

__global__ void __launch_bounds__(256, 2) oproj_ln_dual(
    const __half* __restrict__ AO_0, const __half* __restrict__ Wo_0,
    const float* __restrict__ bo_0, const float* __restrict__ R_0,
    const float* __restrict__ g_0, const float* __restrict__ be_0,
    __half* __restrict__ O_0,
    const __half* __restrict__ AO_1, const __half* __restrict__ Wo_1,
    const float* __restrict__ bo_1, const float* __restrict__ R_1,
    const float* __restrict__ g_1, const float* __restrict__ be_1,
    __half* __restrict__ O_1)
{
    __shared__ __align__(16) __half As[3 * OABUF];
    __shared__ __align__(16) __half Bs[3 * OBBUF];
    __shared__ float psum[64][4];
    __shared__ float psq[64][4];
    __shared__ float murs[64][2];

    int zz = blockIdx.y;
    const __half* AO = zz ? AO_1 : AO_0;
    const __half* Wo = zz ? Wo_1 : Wo_0;
    const float* bo  = zz ? bo_1 : bo_0;
    const float* R   = zz ? R_1  : R_0;
    const float* gam = zz ? g_1  : g_0;
    const float* bet = zz ? be_1 : be_0;
    __half* O = zz ? O_1 : O_0;

    int tid = threadIdx.x, lane = tid & 31, warp = tid >> 5;
    int wm = warp & 1, wn = warp >> 1;
    int gid = lane >> 2, tig = lane & 3;
    int m0 = blockIdx.x * 64;

    int ar0 = tid >> 2, ac = (tid & 3) * 8;
    int br  = tid >> 5, bc = (tid & 31) * 8;

    unsigned As_b = smem_u32(As), Bs_b = smem_u32(Bs);

    int t3 = lane >> 3, lr = lane & 7, tq = t3 & 1, th = t3 >> 1;
    unsigned a_ln = (unsigned)(((wm * 32 + tq * 8 + lr) * OAST + th * 8) * 2);
    unsigned b_ln = (unsigned)(((tq * 8 + lr) * OBST + wn * 64 + th * 8) * 2);

    float acc[2][8][4] = {};

    auto issue = [&](int buf, int k0) {
        unsigned ad = As_b + (unsigned)(buf * OABUF * 2);
        cp16(ad + (unsigned)((ar0 * OAST + ac) * 2),
             AO + (size_t)(m0 + ar0) * DIM + k0 + ac);
        unsigned bd = Bs_b + (unsigned)(buf * OBBUF * 2);
        #pragma unroll
        for (int i = 0; i < 4; i++)
            cp16(bd + (unsigned)(((br + i * 8) * OBST + bc) * 2),
                 Wo + (size_t)(k0 + br + i * 8) * DIM + bc);
    };

    const int T = DIM / 32;   // 8
    issue(0, 0);
    cp_commit();
    issue(1, 32);
    cp_commit();

    int buf = 0;
    for (int it = 0; it < T; it++) {
        if (it + 2 < T) {
            int nb = buf + 2; if (nb >= 3) nb -= 3;
            issue(nb, (it + 2) * 32);
            cp_commit();
            cp_wait2();
        } else if (it + 1 < T) {
            cp_wait1();
        } else {
            cp_wait0();
        }
        __syncthreads();

        unsigned ab = As_b + (unsigned)(buf * OABUF * 2) + a_ln;
        unsigned bb = Bs_b + (unsigned)(buf * OBBUF * 2) + b_ln;
        #pragma unroll
        for (int kk = 0; kk < 2; kk++) {
            unsigned af[2][4];
            ldsm_x4(af[0][0], af[0][1], af[0][2], af[0][3], ab + kk * 32);
            ldsm_x4(af[1][0], af[1][1], af[1][2], af[1][3],
                    ab + 16 * OAST * 2 + kk * 32);
            unsigned bf[8][2];
            #pragma unroll
            for (int bq = 0; bq < 4; bq++) {
                unsigned r0, r1, r2, r3;
                ldsm_x4_t(r0, r1, r2, r3,
                          bb + (unsigned)(kk * (16 * OBST * 2) + bq * 32));
                bf[bq*2][0]   = r0; bf[bq*2][1]   = r1;
                bf[bq*2+1][0] = r2; bf[bq*2+1][1] = r3;
            }
            #pragma unroll
            for (int mt = 0; mt < 2; mt++)
                #pragma unroll
                for (int nt = 0; nt < 8; nt++)
                    mma_f16(acc[mt][nt][0], acc[mt][nt][1],
                            acc[mt][nt][2], acc[mt][nt][3],
                            af[mt][0], af[mt][1], af[mt][2], af[mt][3],
                            bf[nt][0], bf[nt][1]);
        }
        __syncthreads();
        buf++; if (buf == 3) buf = 0;
    }

    #pragma unroll
    for (int mt = 0; mt < 2; mt++) {
        int r1 = m0 + wm * 32 + mt * 16 + gid;
        float s1 = 0.f, q1 = 0.f, s2 = 0.f, q2 = 0.f;
        #pragma unroll
        for (int nt = 0; nt < 8; nt++) {
            int c = wn * 64 + nt * 8 + tig * 2;
            float b0 = bo[c], b1 = bo[c + 1];
            float2 rv1 = *(const float2*)&R[(size_t)r1 * DIM + c];
            float2 rv2 = *(const float2*)&R[(size_t)(r1 + 8) * DIM + c];
            float x0 = acc[mt][nt][0] + b0 + rv1.x;
            float x1 = acc[mt][nt][1] + b1 + rv1.y;
            float x2 = acc[mt][nt][2] + b0 + rv2.x;
            float x3 = acc[mt][nt][3] + b1 + rv2.y;
            acc[mt][nt][0] = x0; acc[mt][nt][1] = x1;
            acc[mt][nt][2] = x2; acc[mt][nt][3] = x3;
            s1 += x0 + x1;
            q1 = fmaf(x0, x0, q1); q1 = fmaf(x1, x1, q1);
            s2 += x2 + x3;
            q2 = fmaf(x2, x2, q2); q2 = fmaf(x3, x3, q2);
        }
        #pragma unroll
        for (int off = 1; off <= 2; off <<= 1) {
            s1 += __shfl_xor_sync(0xFFFFFFFFu, s1, off);
            q1 += __shfl_xor_sync(0xFFFFFFFFu, q1, off);
            s2 += __shfl_xor_sync(0xFFFFFFFFu, s2, off);
            q2 += __shfl_xor_sync(0xFFFFFFFFu, q2, off);
        }
        if (tig == 0) {
            int rl = wm * 32 + mt * 16 + gid;
            psum[rl][wn] = s1;  psq[rl][wn] = q1;
            psum[rl + 8][wn] = s2;  psq[rl + 8][wn] = q2;
        }
    }
    __syncthreads();

    if (tid < 64) {
        float ss = psum[tid][0] + psum[tid][1] + psum[tid][2] + psum[tid][3];
        float qq = psq[tid][0] + psq[tid][1] + psq[tid][2] + psq[tid][3];
        float mu = ss * (1.f / 256.f);
        float var = qq * (1.f / 256.f) - mu * mu;
        murs[tid][0] = mu;
        murs[tid][1] = rsqrtf(var + 1e-5f);
    }
    __syncthreads();

    #pragma unroll
    for (int mt = 0; mt < 2; mt++) {
        int rl = wm * 32 + mt * 16 + gid;
        float mu1 = murs[rl][0],     rs1 = murs[rl][1];
        float mu2 = murs[rl + 8][0], rs2 = murs[rl + 8][1];
        int r1 = m0 + rl;
        #pragma unroll
        for (int nt = 0; nt < 8; nt++) {
            int c = wn * 64 + nt * 8 + tig * 2;
            float g0 = gam[c], g1 = gam[c + 1];
            float e0 = bet[c], e1 = bet[c + 1];
            *(unsigned*)&O[(size_t)r1 * DIM + c] =
                f2h2((acc[mt][nt][0] - mu1) * rs1 * g0 + e0,
                     (acc[mt][nt][1] - mu1) * rs1 * g1 + e1);
            *(unsigned*)&O[(size_t)(r1 + 8) * DIM + c] =
                f2h2((acc[mt][nt][2] - mu2) * rs2 * g0 + e0,
                     (acc[mt][nt][3] - mu2) * rs2 * g1 + e1);
        }
    }
}

// ---------------------------------------------------------------------------
// FP16 flash attention (R9, frozen — best measured 96.7us).
// ---------------------------------------------------------------------------
#define KST 40
#define KVBUF (64 * KST)

__global__ void __launch_bounds__(256) attn_f16(
    const __half* __restrict__ OutImg, const __half* __restrict__ OutTxt,
    __half* __restrict__ AOi, __half* __restrict__ AOt)
{
    __shared__ __align__(16) __half Ks[2 * KVBUF];
    __shared__ __align__(16) __half Vs[2 * KVBUF];

    int tid = threadIdx.x, lane = tid & 31, warp = tid >> 5;
    int gid = lane >> 2, tig = lane & 3;
    int zz = blockIdx.z;
    int dir = zz >> 4, b = zz & 15;
    const __half* Q  = dir ? OutTxt : OutImg;
    const __half* Kp = (dir ? OutImg : OutTxt) + 256;
    const __half* Vp = (dir ? OutImg : OutTxt) + 512;
    __half* O = dir ? AOt : AOi;
    const int ldin = 768;

    int h = blockIdx.y;
    int q0 = blockIdx.x * 256 + warp * 32;
    int hoff = h * HDIM;
    size_t rowQ = (size_t)b * SEQ + q0;

    int s_row = tid >> 2, s_c = (tid & 3) * 8;

    unsigned Ks_b = smem_u32(Ks), Vs_b = smem_u32(Vs);

    int t3 = lane >> 3, lr = lane & 7, tq = t3 & 1, th = t3 >> 1;
    unsigned kv_ln = (unsigned)(((tq * 8 + lr) * KST + th * 8) * 2);

    const __half2 c2h = __float2half2_rn(0.25503526f);
    unsigned qf[2][2][4];
    #pragma unroll
    for (int rs = 0; rs < 2; rs++) {
        #pragma unroll
        for (int kk = 0; kk < 2; kk++) {
            const __half* q1 = Q + (rowQ + rs * 16 + gid) * ldin + hoff + kk * 16 + tig * 2;
            const __half* q2 = q1 + 8 * ldin;
            __half2 v;
            v = __hmul2(*(const __half2*)q1,       c2h); qf[rs][kk][0] = *(unsigned*)&v;
            v = __hmul2(*(const __half2*)q2,       c2h); qf[rs][kk][1] = *(unsigned*)&v;
            v = __hmul2(*(const __half2*)(q1 + 8), c2h); qf[rs][kk][2] = *(unsigned*)&v;
            v = __hmul2(*(const __half2*)(q2 + 8), c2h); qf[rs][kk][3] = *(unsigned*)&v;
        }
    }

    const unsigned ONES = 0x3C003C00u;
    float o[2][4][4] = {};
    float ol[2][4] = {};

    auto issue = [&](int buf, int kt) {
        size_t g = ((size_t)b * SEQ + kt + s_row) * ldin + hoff + s_c;
        unsigned off = (unsigned)(buf * KVBUF * 2) + (unsigned)((s_row * KST + s_c) * 2);
        cp16(Ks_b + off, Kp + g);
        cp16(Vs_b + off, Vp + g);
    };

    issue(0, 0);
    cp_commit();

    const int T = SEQ / 64;
    for (int it = 0; it < T; it++) {
        if (it + 1 < T) {
            issue((it + 1) & 1, (it + 1) * 64);
            cp_commit();
            cp_wait1();
        } else {
            cp_wait0();
        }
        __syncthreads();

        unsigned kb = Ks_b + (unsigned)((it & 1) * KVBUF * 2) + kv_ln;
        unsigned vb = Vs_b + (unsigned)((it & 1) * KVBUF * 2) + kv_ln;

        float s0[8][4] = {}, s1[8][4] = {};
        #pragma unroll
        for (int kk = 0; kk < 2; kk++) {
            #pragma unroll
            for (int np = 0; np < 4; np++) {
                unsigned r0, r1, r2, r3;
                ldsm_x4(r0, r1, r2, r3,
                        kb + (unsigned)((np * 16 * KST + kk * 16) * 2));
                mma_f16(s0[np*2][0], s0[np*2][1], s0[np*2][2], s0[np*2][3],
                        qf[0][kk][0], qf[0][kk][1], qf[0][kk][2], qf[0][kk][3], r0, r2);
                mma_f16(s0[np*2+1][0], s0[np*2+1][1], s0[np*2+1][2], s0[np*2+1][3],
                        qf[0][kk][0], qf[0][kk][1], qf[0][kk][2], qf[0][kk][3], r1, r3);
                mma_f16(s1[np*2][0], s1[np*2][1], s1[np*2][2], s1[np*2][3],
                        qf[1][kk][0], qf[1][kk][1], qf[1][kk][2], qf[1][kk][3], r0, r2);
                mma_f16(s1[np*2+1][0], s1[np*2+1][1], s1[np*2+1][2], s1[np*2+1][3],
                        qf[1][kk][0], qf[1][kk][1], qf[1][kk][2], qf[1][kk][3], r1, r3);
            }
        }

        unsigned pa0[4][4], pa1[4][4];
        #pragma unroll
        for (int kk = 0; kk < 4; kk++) {
            pa0[kk][0] = h2ex2(f2h2(s0[2*kk][0],   s0[2*kk][1]));
            pa0[kk][1] = h2ex2(f2h2(s0[2*kk][2],   s0[2*kk][3]));
            pa0[kk][2] = h2ex2(f2h2(s0[2*kk+1][0], s0[2*kk+1][1]));
            pa0[kk][3] = h2ex2(f2h2(s0[2*kk+1][2], s0[2*kk+1][3]));
            pa1[kk][0] = h2ex2(f2h2(s1[2*kk][0],   s1[2*kk][1]));
            pa1[kk][1] = h2ex2(f2h2(s1[2*kk][2],   s1[2*kk][3]));
            pa1[kk][2] = h2ex2(f2h2(s1[2*kk+1][0], s1[2*kk+1][1]));
            pa1[kk][3] = h2ex2(f2h2(s1[2*kk+1][2], s1[2*kk+1][3]));
        }

        #pragma unroll
        for (int kk = 0; kk < 4; kk++) {
            #pragma unroll
            for (int dg = 0; dg < 2; dg++) {
                unsigned r0, r1, r2, r3;
                ldsm_x4_t(r0, r1, r2, r3,
                          vb + (unsigned)((kk * 16 * KST + dg * 16) * 2));
                mma_f16(o[0][dg*2][0], o[0][dg*2][1], o[0][dg*2][2], o[0][dg*2][3],
                        pa0[kk][0], pa0[kk][1], pa0[kk][2], pa0[kk][3], r0, r1);
                mma_f16(o[0][dg*2+1][0], o[0][dg*2+1][1], o[0][dg*2+1][2], o[0][dg*2+1][3],
                        pa0[kk][0], pa0[kk][1], pa0[kk][2], pa0[kk][3], r2, r3);
                mma_f16(o[1][dg*2][0], o[1][dg*2][1], o[1][dg*2][2], o[1][dg*2][3],
                        pa1[kk][0], pa1[kk][1], pa1[kk][2], pa1[kk][3], r0, r1);
                mma_f16(o[1][dg*2+1][0], o[1][dg*2+1][1], o[1][dg*2+1][2], o[1][dg*2+1][3],
                        pa1[kk][0], pa1[kk][1], pa1[kk][2], pa1[kk][3], r2, r3);
            }
            mma_f16(ol[0][0], ol[0][1], ol[0][2], ol[0][3],
                    pa0[kk][0], pa0[kk][1], pa0[kk][2], pa0[kk][3], ONES, ONES);
            mma_f16(ol[1][0], ol[1][1], ol[1][2], ol[1][3],
                    pa1[kk][0], pa1[kk][1], pa1[kk][2], pa1[kk][3], ONES, ONES);
        }
        __syncthreads();
    }

    #pragma unroll
    for (int rs = 0; rs < 2; rs++) {
        float inv1 = 1.f / ol[rs][0];
        float inv2 = 1.f / ol[rs][2];
        size_t r1 = rowQ + rs * 16 + gid;
        #pragma unroll
        for (int nt = 0; nt < 4; nt++) {
            int col = hoff + nt * 8 + tig * 2;
            *(unsigned*)&O[r1 * DIM + col] =
                f2h2(o[rs][nt][0] * inv1, o[rs][nt][1] * inv1);
            *(unsigned*)&O[(r1 + 8) * DIM + col] =
                f2h2(o[rs][nt][2] * inv2, o[rs][nt][3] * inv2);
        }
    }
}

// ---------------------------------------------------------------------------
extern "C" void kernel_launch(void* const* d_in, const int* in_sizes, int n_in,
                              void* d_out, int out_size)
{
    const float* img_common = (const float*)d_in[0];
    const float* txt_common = (const float*)d_in[1];
    const float* img_sp     = (const float*)d_in[2];
    const float* txt_sp     = (const float*)d_in[3];
    const float* i2t_wq = (const float*)d_in[4];
    const float* i2t_bq = (const float*)d_in[5];
    const float* i2t_wk = (const float*)d_in[6];
    const float* i2t_bk = (const float*)d_in[7];
    const float* i2t_wv = (const float*)d_in[8];
    const float* i2t_bv = (const float*)d_in[9];
    const float* i2t_wo = (const float*)d_in[10];
    const float* i2t_bo = (const float*)d_in[11];
    const float* t2i_wq = (const float*)d_in[12];
    const float* t2i_bq = (const float*)d_in[13];
    const float* t2i_wk = (const float*)d_in[14];
    const float* t2i_bk = (const float*)d_in[15];
    const float* t2i_wv = (const float*)d_in[16];
    const float* t2i_bv = (const float*)d_in[17];
    const float* t2i_wo = (const float*)d_in[18];
    const float* t2i_bo = (const float*)d_in[19];
    const float* ln_img_g = (const float*)d_in[20];
    const float* ln_img_b = (const float*)d_in[21];
    const float* ln_txt_g = (const float*)d_in[22];
    const float* ln_txt_b = (const float*)d_in[23];
    const float* enh_w = (const float*)d_in[24];
    const float* enh_b = (const float*)d_in[25];
    const float* inc_w = (const float*)d_in[26];
    const float* inc_b = (const float*)d_in[27];

    float* out = (float*)d_out;
    float* out_enh = out;
    float* out_inc = out + BUFSZ;
    float* out_img = out + BUFSZ + 4096;
    float* out_txt = out + BUFSZ + 8192;

    unsigned char* pool = nullptr;
    cudaGetSymbolAddress((void**)&pool, g_pool);
    __half* img_h  = (__half*)(pool + P_IMG_H);
    __half* txt_h  = (__half*)(pool + P_TXT_H);
    __half* OutImg = (__half*)(pool + P_OUTIMG);
    __half* OutTxt = (__half*)(pool + P_OUTTXT);
    __half* AOi    = (__half*)(pool + P_AOI);
    __half* AOt    = (__half*)(pool + P_AOT);
    __half* QImg   = (__half*)(pool + P_QIMG);
    __half* QTxt   = (__half*)(pool + P_QTXT);
    __half* Wimg   = (__half*)(pool + P_WIMG);
    __half* Wtxt   = (__half*)(pool + P_WTXT);
    __half* WoI    = (__half*)(pool + P_WOI);
    __half* WoT    = (__half*)(pool + P_WOT);
    __half* Wenh   = (__half*)(pool + P_WENH);
    float*  bimg   = (float*) (pool + P_BIMG);
    float*  btxt   = (float*) (pool + P_BTXT);

    // --- prep + inconsistency head, ONE launch
    prep_all_kernel<<<PREP_FLAT_BLOCKS + BATCH, 256>>>(
        img_common, img_h, txt_common, txt_h,
        i2t_wq, i2t_wk, i2t_wv, t2i_wq, t2i_wk, t2i_wv,
        i2t_bq, i2t_bk, i2t_bv, t2i_bq, t2i_bk, t2i_bv,
        i2t_wo, t2i_wo, enh_w,
        Wimg, Wtxt, WoI, WoT, Wenh, bimg, btxt,
        img_sp, txt_sp, inc_w, inc_b, out_inc, out_img, out_txt);

    // --- fused QKV GEMMs, both modalities in one launch (128x128 tiles)
    dim3 gq(768 / 128, MROWS / 128, 2);   // (6, 128, 2)
    gemm_f16_dual<1><<<gq, 256>>>(
        img_h, img_h, Wimg, bimg, OutImg,
        txt_h, txt_h, Wtxt, btxt, OutTxt,
        DIM, 768, 768, DIM);

    // --- attention, both directions in one launch
    dim3 ga(SEQ / 256, NHEADS, 2 * BATCH);
    attn_f16<<<ga, 256>>>(OutImg, OutTxt, AOi, AOt);

    // --- fused O-proj + residual(fp32) + LayerNorm
    dim3 go(MROWS / 64, 2);               // (256, 2)
    oproj_ln_dual<<<go, 256>>>(
        AOi, WoI, i2t_bo, img_common, ln_img_g, ln_img_b, QImg,
        AOt, WoT, t2i_bo, txt_common, ln_txt_g, ln_txt_b, QTxt);

    // --- enhancement: concat [16384,512] @ [512,256] -> fp32 out
    dim3 ge(DIM / 128, MROWS / 128, 1);   // (2, 128, 1)
    gemm_f16_dual<0><<<ge, 256>>>(
        QImg, QTxt, Wenh, enh_b, out_enh,
        QImg, QTxt, Wenh, enh_b, out_enh,
        DIM, DIM, DIM, 2 * DIM);
}